// round 1
// baseline (speedup 1.0000x reference)
#include <cuda_runtime.h>
#include <cuda_bf16.h>
#include <math.h>
#include <stdint.h>
#include <stddef.h>

// Problem dims
#define BB 2
#define SS 2048
#define DD 192
#define HH 16
#define HDIM 128

// Scratch (device globals; no runtime allocation allowed)
__device__ float g_q[BB * HH * SS * HDIM];     // [b][h][s][hd]
__device__ float g_k[BB * HH * SS * HDIM];
__device__ float g_v[BB * HH * SS * HDIM];
__device__ float g_attn[BB * SS * HH * HDIM];  // [b][s][h*HD]

// ---------------------------------------------------------------------------
// Kernel 1: QKV projection.  C[m][n] = sum_k x[m][k] * w[n][k]
// x: [4096, 192], w: [2048, 192].  grid (64, 32, 3), block 256.
// Writes into g_q/g_k/g_v with [b][h][s][hd] layout.
// ---------------------------------------------------------------------------
__global__ __launch_bounds__(256) void qkv_kernel(
    const float* __restrict__ x,
    const float* __restrict__ wq,
    const float* __restrict__ wk,
    const float* __restrict__ wv)
{
    __shared__ float sA[32][68];  // k-major: sA[k][m]
    __shared__ float sW[32][68];  // k-major: sW[k][n]
    const int tid = threadIdx.x;
    const int m0 = blockIdx.x * 64;
    const int n0 = blockIdx.y * 64;
    const int z = blockIdx.z;
    const float* w = (z == 0) ? wq : (z == 1) ? wk : wv;
    float* dst = (z == 0) ? g_q : (z == 1) ? g_k : g_v;
    const int r0 = (tid >> 4) * 4;
    const int c0 = (tid & 15) * 4;
    float acc[4][4] = {};

    for (int kb = 0; kb < 192; kb += 32) {
        for (int i = tid; i < 2048; i += 256) {
            int r = i >> 5, c = i & 31;
            sA[c][r] = x[(size_t)(m0 + r) * 192 + kb + c];
            sW[c][r] = w[(size_t)(n0 + r) * 192 + kb + c];
        }
        __syncthreads();
        #pragma unroll
        for (int k = 0; k < 32; k++) {
            float4 a = *(const float4*)&sA[k][r0];
            float4 b = *(const float4*)&sW[k][c0];
            float av[4] = {a.x, a.y, a.z, a.w};
            float bv[4] = {b.x, b.y, b.z, b.w};
            #pragma unroll
            for (int i = 0; i < 4; i++)
                #pragma unroll
                for (int j = 0; j < 4; j++)
                    acc[i][j] += av[i] * bv[j];
        }
        __syncthreads();
    }

    #pragma unroll
    for (int i = 0; i < 4; i++) {
        int m = m0 + r0 + i;
        int b = m >> 11, s = m & 2047;
        int n = n0 + c0;
        int h = n >> 7, hd = n & 127;
        float4 v = make_float4(acc[i][0], acc[i][1], acc[i][2], acc[i][3]);
        *(float4*)&dst[((size_t)(b * HH + h) * SS + s) * HDIM + hd] = v;
    }
}

// ---------------------------------------------------------------------------
// Kernel 2: per-head RMSNorm + RoPE for q and k, in place.
// grid (B*S*H) blocks, 128 threads (one per hd).
// ---------------------------------------------------------------------------
__global__ __launch_bounds__(128) void normrope_kernel(
    const float* __restrict__ qw, const float* __restrict__ kw)
{
    __shared__ float sq[128], sk[128], red[8];
    const int bs = blockIdx.x;
    const int h = bs & 15;
    const int s = (bs >> 4) & 2047;
    const int b = bs >> 15;
    const int hd = threadIdx.x;
    const size_t base = ((size_t)(b * HH + h) * SS + s) * HDIM;

    float qv = g_q[base + hd];
    float kv = g_k[base + hd];
    float q2 = qv * qv, k2 = kv * kv;
    #pragma unroll
    for (int off = 16; off; off >>= 1) {
        q2 += __shfl_xor_sync(0xffffffffu, q2, off);
        k2 += __shfl_xor_sync(0xffffffffu, k2, off);
    }
    if ((hd & 31) == 0) { red[hd >> 5] = q2; red[4 + (hd >> 5)] = k2; }
    __syncthreads();
    float qs = red[0] + red[1] + red[2] + red[3];
    float ks = red[4] + red[5] + red[6] + red[7];
    float qr = rsqrtf(qs * (1.0f / 128.0f) + 1e-6f);
    float kr = rsqrtf(ks * (1.0f / 128.0f) + 1e-6f);
    float qn = qv * qr * qw[hd];
    float kn = kv * kr * kw[hd];
    sq[hd] = qn; sk[hd] = kn;
    __syncthreads();

    // RoPE: angle = s * theta^(-(hd mod 64)/64).  Double arg-reduction keeps
    // accuracy even under --use_fast_math (__sinf is bad for |x| ~ 2000).
    int p = hd & 63;
    double inv = exp((double)p * -0.21586735246819178);  // -ln(1e6)/64
    double angd = fmod((double)s * inv, 6.283185307179586476925287);
    float ang = (float)angd;
    float sn = sinf(ang), cs = cosf(ang);
    float qrot = (hd < 64) ? -sq[hd + 64] : sq[hd - 64];
    float krot = (hd < 64) ? -sk[hd + 64] : sk[hd - 64];
    g_q[base + hd] = qn * cs + qrot * sn;
    g_k[base + hd] = kn * cs + krot * sn;
}

// ---------------------------------------------------------------------------
// Kernel 3: flash attention.  grid (S/64, H, B), block 256.
// 64-query tile, loop over 32 key tiles of 64; online softmax.
// K and V share one smem buffer (85 KB dyn smem -> 2 blocks/SM).
// ---------------------------------------------------------------------------
#define QS 132              // padded row stride (floats)
#define ATTN_SMEM_BYTES ((2 * 64 * QS + 64 * 65 + 3 * 64) * 4)

__global__ __launch_bounds__(256, 2) void attn_kernel(const float* __restrict__ mask)
{
    extern __shared__ float sm[];
    float* sQ  = sm;                 // 64 x QS
    float* sKV = sm + 64 * QS;       // 64 x QS (K, then reused for V)
    float* sP  = sKV + 64 * QS;      // 64 x 65 scores / probs
    float* sM  = sP + 64 * 65;       // running max
    float* sL  = sM + 64;            // running denom
    float* sAl = sL + 64;            // rescale factor per tile

    const int tid = threadIdx.x;
    const int q0 = blockIdx.x * 64;
    const int h = blockIdx.y, b = blockIdx.z;
    const size_t bh = (size_t)(b * HH + h) * SS * HDIM;
    const float* Qg = g_q + bh;
    const float* Kg = g_k + bh;
    const float* Vg = g_v + bh;
    const float* mbase = mask + (size_t)b * SS * SS;
    const float scale = 0.08838834764831845f;  // 128^-0.5

    // load Q tile
    for (int i = tid; i < 2048; i += 256) {
        int r = i >> 5, c4 = (i & 31) * 4;
        *(float4*)&sQ[r * QS + c4] = *(const float4*)&Qg[(size_t)(q0 + r) * HDIM + c4];
    }
    if (tid < 64) { sM[tid] = -1e30f; sL[tid] = 0.0f; }

    float o[4][8];
    #pragma unroll
    for (int i = 0; i < 4; i++)
        #pragma unroll
        for (int j = 0; j < 8; j++) o[i][j] = 0.0f;

    const int rg = tid >> 4;      // row lane 0..15  -> rows rg + i*16
    const int cg = tid & 15;      // col lane 0..15  -> cols cg + j*16
    const int d0 = cg * 8;        // output dims d0..d0+7
    __syncthreads();

    for (int kt = 0; kt < 32; kt++) {
        const int k0 = kt * 64;
        // load K tile
        for (int i = tid; i < 2048; i += 256) {
            int r = i >> 5, c4 = (i & 31) * 4;
            *(float4*)&sKV[r * QS + c4] = *(const float4*)&Kg[(size_t)(k0 + r) * HDIM + c4];
        }
        __syncthreads();

        // scores: 4x4 per thread over d = 0..127
        float acc[4][4] = {};
        #pragma unroll 8
        for (int d4 = 0; d4 < 128; d4 += 4) {
            float4 a[4], kk[4];
            #pragma unroll
            for (int i = 0; i < 4; i++) a[i]  = *(const float4*)&sQ [(rg + i * 16) * QS + d4];
            #pragma unroll
            for (int j = 0; j < 4; j++) kk[j] = *(const float4*)&sKV[(cg + j * 16) * QS + d4];
            #pragma unroll
            for (int i = 0; i < 4; i++)
                #pragma unroll
                for (int j = 0; j < 4; j++) {
                    acc[i][j] += a[i].x * kk[j].x;
                    acc[i][j] += a[i].y * kk[j].y;
                    acc[i][j] += a[i].z * kk[j].z;
                    acc[i][j] += a[i].w * kk[j].w;
                }
        }
        // write scaled+masked scores
        #pragma unroll
        for (int i = 0; i < 4; i++) {
            int qr = rg + i * 16;
            const float* mr = &mbase[(size_t)(q0 + qr) * SS + k0];
            #pragma unroll
            for (int j = 0; j < 4; j++) {
                int c = cg + j * 16;
                sP[qr * 65 + c] = acc[i][j] * scale + mr[c];
            }
        }
        __syncthreads();

        // online softmax stats, one thread per row
        if (tid < 64) {
            const int r = tid;
            float mo = sM[r], mx = mo;
            #pragma unroll 8
            for (int c = 0; c < 64; c++) mx = fmaxf(mx, sP[r * 65 + c]);
            float al = __expf(mo - mx);
            float sum = 0.0f;
            #pragma unroll 8
            for (int c = 0; c < 64; c++) {
                float pv = __expf(sP[r * 65 + c] - mx);
                sP[r * 65 + c] = pv;
                sum += pv;
            }
            sL[r] = sL[r] * al + sum;
            sM[r] = mx;
            sAl[r] = al;
        }
        __syncthreads();

        // load V tile into the same buffer
        for (int i = tid; i < 2048; i += 256) {
            int r = i >> 5, c4 = (i & 31) * 4;
            *(float4*)&sKV[r * QS + c4] = *(const float4*)&Vg[(size_t)(k0 + r) * HDIM + c4];
        }
        __syncthreads();

        // rescale accumulators, then O += P * V
        float al[4];
        #pragma unroll
        for (int i = 0; i < 4; i++) al[i] = sAl[rg + i * 16];
        #pragma unroll
        for (int i = 0; i < 4; i++)
            #pragma unroll
            for (int j = 0; j < 8; j++) o[i][j] *= al[i];

        #pragma unroll 4
        for (int t = 0; t < 64; t++) {
            float4 v0 = *(const float4*)&sKV[t * QS + d0];
            float4 v1 = *(const float4*)&sKV[t * QS + d0 + 4];
            #pragma unroll
            for (int i = 0; i < 4; i++) {
                float pv = sP[(rg + i * 16) * 65 + t];
                o[i][0] += pv * v0.x; o[i][1] += pv * v0.y;
                o[i][2] += pv * v0.z; o[i][3] += pv * v0.w;
                o[i][4] += pv * v1.x; o[i][5] += pv * v1.y;
                o[i][6] += pv * v1.z; o[i][7] += pv * v1.w;
            }
        }
        __syncthreads();
    }

    // finalize: divide by denom, write [b][s][h*HD + d]
    #pragma unroll
    for (int i = 0; i < 4; i++) {
        int r = rg + i * 16;
        float li = 1.0f / sL[r];
        size_t ob = (size_t)(b * SS + q0 + r) * (HH * HDIM) + h * HDIM + d0;
        float4 u0 = make_float4(o[i][0] * li, o[i][1] * li, o[i][2] * li, o[i][3] * li);
        float4 u1 = make_float4(o[i][4] * li, o[i][5] * li, o[i][6] * li, o[i][7] * li);
        *(float4*)&g_attn[ob] = u0;
        *(float4*)&g_attn[ob + 4] = u1;
    }
}

// ---------------------------------------------------------------------------
// Kernel 4: output projection.  out[m][n] = sum_k attn[m][k] * wo[n][k]
// attn: [4096, 2048], wo: [192, 2048].  grid (64, 3), block 256.
// ---------------------------------------------------------------------------
__global__ __launch_bounds__(256) void oproj_kernel(
    const float* __restrict__ wo, float* __restrict__ out)
{
    __shared__ float sA[32][68];
    __shared__ float sW[32][68];
    const int tid = threadIdx.x;
    const int m0 = blockIdx.x * 64;
    const int n0 = blockIdx.y * 64;
    const int r0 = (tid >> 4) * 4;
    const int c0 = (tid & 15) * 4;
    float acc[4][4] = {};

    for (int kb = 0; kb < 2048; kb += 32) {
        for (int i = tid; i < 2048; i += 256) {
            int r = i >> 5, c = i & 31;
            sA[c][r] = g_attn[(size_t)(m0 + r) * 2048 + kb + c];
            sW[c][r] = wo[(size_t)(n0 + r) * 2048 + kb + c];
        }
        __syncthreads();
        #pragma unroll
        for (int k = 0; k < 32; k++) {
            float4 a = *(const float4*)&sA[k][r0];
            float4 b = *(const float4*)&sW[k][c0];
            float av[4] = {a.x, a.y, a.z, a.w};
            float bv[4] = {b.x, b.y, b.z, b.w};
            #pragma unroll
            for (int i = 0; i < 4; i++)
                #pragma unroll
                for (int j = 0; j < 4; j++)
                    acc[i][j] += av[i] * bv[j];
        }
        __syncthreads();
    }

    #pragma unroll
    for (int i = 0; i < 4; i++) {
        int m = m0 + r0 + i;
        float4 v = make_float4(acc[i][0], acc[i][1], acc[i][2], acc[i][3]);
        *(float4*)&out[(size_t)m * DD + n0 + c0] = v;
    }
}

// ---------------------------------------------------------------------------
// Inputs (metadata order): x, mask0, wq, wk, wv, wo, q_norm_w, k_norm_w
// ---------------------------------------------------------------------------
extern "C" void kernel_launch(void* const* d_in, const int* in_sizes, int n_in,
                              void* d_out, int out_size)
{
    const float* x     = (const float*)d_in[0];
    const float* mask0 = (const float*)d_in[1];
    const float* wq    = (const float*)d_in[2];
    const float* wk    = (const float*)d_in[3];
    const float* wv    = (const float*)d_in[4];
    const float* wo    = (const float*)d_in[5];
    const float* qnw   = (const float*)d_in[6];
    const float* knw   = (const float*)d_in[7];
    float* out = (float*)d_out;

    cudaFuncSetAttribute(attn_kernel, cudaFuncAttributeMaxDynamicSharedMemorySize,
                         ATTN_SMEM_BYTES);

    qkv_kernel<<<dim3(64, 32, 3), 256>>>(x, wq, wk, wv);
    normrope_kernel<<<BB * SS * HH, 128>>>(qnw, knw);
    attn_kernel<<<dim3(SS / 64, HH, BB), 256, ATTN_SMEM_BYTES>>>(mask0);
    oproj_kernel<<<dim3(64, 3), 256>>>(wo, out);
}

// round 3
// speedup vs baseline: 1.1423x; 1.1423x over previous
// R3 == R2 kernel (R2 bench hit transient "device busy" infra failure before launch)
#include <cuda_runtime.h>
#include <cuda_bf16.h>
#include <math.h>
#include <stdint.h>
#include <stddef.h>

// Problem dims
#define BB 2
#define SS 2048
#define DD 192
#define HH 16
#define HDIM 128

typedef unsigned long long u64;

// Packed f32x2 helpers (SASS FFMA2 — ptxas never emits this from C++)
__device__ __forceinline__ u64 fma2(u64 a, u64 b, u64 c) {
    u64 d; asm("fma.rn.f32x2 %0, %1, %2, %3;" : "=l"(d) : "l"(a), "l"(b), "l"(c)); return d;
}
__device__ __forceinline__ u64 mul2(u64 a, u64 b) {
    u64 d; asm("mul.rn.f32x2 %0, %1, %2;" : "=l"(d) : "l"(a), "l"(b)); return d;
}
__device__ __forceinline__ float f2sum(u64 v) {
    float lo, hi; asm("mov.b64 {%0, %1}, %2;" : "=f"(lo), "=f"(hi) : "l"(v)); return lo + hi;
}
__device__ __forceinline__ void f2unpack(u64 v, float& lo, float& hi) {
    asm("mov.b64 {%0, %1}, %2;" : "=f"(lo), "=f"(hi) : "l"(v));
}
__device__ __forceinline__ u64 pack2(float lo, float hi) {
    u64 d; asm("mov.b64 %0, {%1, %2};" : "=l"(d) : "f"(lo), "f"(hi)); return d;
}

// Scratch (device globals; no runtime allocation allowed)
__device__ float g_q[BB * HH * SS * HDIM];     // [b][h][s][hd]
__device__ float g_k[BB * HH * SS * HDIM];
__device__ float g_v[BB * HH * SS * HDIM];
__device__ float g_attn[BB * SS * HH * HDIM];  // [b][s][h*HD]
__device__ float g_part[4][BB * SS * DD];      // split-K partials for oproj

// ---------------------------------------------------------------------------
// Kernel 1: QKV projection.  C[m][n] = sum_k x[m][k] * w[n][k]
// x: [4096, 192], w: [2048, 192].  grid (64, 32, 3), block 256.
// smem k-contiguous + XOR swizzle, f32x2 packed along k.
// ---------------------------------------------------------------------------
__global__ __launch_bounds__(256) void qkv_kernel(
    const float* __restrict__ x,
    const float* __restrict__ wq,
    const float* __restrict__ wk,
    const float* __restrict__ wv)
{
    __shared__ __align__(16) float sA[64 * 32];
    __shared__ __align__(16) float sW[64 * 32];
    const int tid = threadIdx.x;
    const int m0 = blockIdx.x * 64;
    const int n0 = blockIdx.y * 64;
    const int z = blockIdx.z;
    const float* w = (z == 0) ? wq : (z == 1) ? wk : wv;
    float* dst = (z == 0) ? g_q : (z == 1) ? g_k : g_v;
    const int rg = tid >> 4, cg = tid & 15;
    const int r0 = rg * 4, c0 = cg * 4;
    const int swzA = (rg & 7) << 2;
    const int swzB = (cg & 7) << 2;
    u64 acc[4][4] = {};

    for (int kb = 0; kb < 192; kb += 32) {
        #pragma unroll
        for (int it = 0; it < 2; it++) {
            int idx = tid + it * 256;
            int r = idx >> 3, kq = (idx & 7) * 4;
            int sw = r * 32 + (kq ^ (((r >> 2) & 7) << 2));
            *(float4*)&sA[sw] = *(const float4*)&x[(size_t)(m0 + r) * 192 + kb + kq];
            *(float4*)&sW[sw] = *(const float4*)&w[(size_t)(n0 + r) * 192 + kb + kq];
        }
        __syncthreads();
        #pragma unroll
        for (int k4 = 0; k4 < 32; k4 += 4) {
            ulonglong2 A[4], B[4];
            #pragma unroll
            for (int i = 0; i < 4; i++)
                A[i] = *(const ulonglong2*)&sA[(r0 + i) * 32 + (k4 ^ swzA)];
            #pragma unroll
            for (int j = 0; j < 4; j++)
                B[j] = *(const ulonglong2*)&sW[(c0 + j) * 32 + (k4 ^ swzB)];
            #pragma unroll
            for (int i = 0; i < 4; i++)
                #pragma unroll
                for (int j = 0; j < 4; j++) {
                    acc[i][j] = fma2(A[i].x, B[j].x, acc[i][j]);
                    acc[i][j] = fma2(A[i].y, B[j].y, acc[i][j]);
                }
        }
        __syncthreads();
    }

    #pragma unroll
    for (int i = 0; i < 4; i++) {
        int m = m0 + r0 + i;
        int b = m >> 11, s = m & 2047;
        int n = n0 + c0;
        int h = n >> 7, hd = n & 127;
        float4 v = make_float4(f2sum(acc[i][0]), f2sum(acc[i][1]),
                               f2sum(acc[i][2]), f2sum(acc[i][3]));
        *(float4*)&dst[((size_t)(b * HH + h) * SS + s) * HDIM + hd] = v;
    }
}

// ---------------------------------------------------------------------------
// Kernel 2: per-head RMSNorm + RoPE for q and k, in place.
// ---------------------------------------------------------------------------
__global__ __launch_bounds__(128) void normrope_kernel(
    const float* __restrict__ qw, const float* __restrict__ kw)
{
    __shared__ float sq[128], sk[128], red[8];
    const int bs = blockIdx.x;
    const int h = bs & 15;
    const int s = (bs >> 4) & 2047;
    const int b = bs >> 15;
    const int hd = threadIdx.x;
    const size_t base = ((size_t)(b * HH + h) * SS + s) * HDIM;

    float qv = g_q[base + hd];
    float kv = g_k[base + hd];
    float q2 = qv * qv, k2 = kv * kv;
    #pragma unroll
    for (int off = 16; off; off >>= 1) {
        q2 += __shfl_xor_sync(0xffffffffu, q2, off);
        k2 += __shfl_xor_sync(0xffffffffu, k2, off);
    }
    if ((hd & 31) == 0) { red[hd >> 5] = q2; red[4 + (hd >> 5)] = k2; }
    __syncthreads();
    float qs = red[0] + red[1] + red[2] + red[3];
    float ks = red[4] + red[5] + red[6] + red[7];
    float qr = rsqrtf(qs * (1.0f / 128.0f) + 1e-6f);
    float kr = rsqrtf(ks * (1.0f / 128.0f) + 1e-6f);
    float qn = qv * qr * qw[hd];
    float kn = kv * kr * kw[hd];
    sq[hd] = qn; sk[hd] = kn;
    __syncthreads();

    int p = hd & 63;
    double inv = exp((double)p * -0.21586735246819178);  // -ln(1e6)/64
    double angd = fmod((double)s * inv, 6.283185307179586476925287);
    float ang = (float)angd;
    float sn = sinf(ang), cs = cosf(ang);
    float qrot = (hd < 64) ? -sq[hd + 64] : sq[hd - 64];
    float krot = (hd < 64) ? -sk[hd + 64] : sk[hd - 64];
    g_q[base + hd] = qn * cs + qrot * sn;
    g_k[base + hd] = kn * cs + krot * sn;
}

// ---------------------------------------------------------------------------
// Kernel 3: flash attention, f32x2 packed.  grid (32, 16, 2), block 256.
// sQ/sKV: [64][128] with 2-level XOR swizzle; sPd: probs stored DUPLICATED
// ((p,p) pairs) so PV reads packed operands with a single LDS.
// ---------------------------------------------------------------------------
#define AT_SMEM_FLOATS (3 * 64 * 128 + 3 * 64)
#define AT_SMEM_BYTES (AT_SMEM_FLOATS * 4)

__device__ __forceinline__ int swz128(int r, int d4) {
    return r * 128 + (d4 ^ ((r & 7) << 2) ^ (((d4 >> 5) & 1) << 2));
}

__global__ __launch_bounds__(256, 2) void attn_kernel(const float* __restrict__ mask)
{
    extern __shared__ __align__(16) float sm[];
    float* sQ  = sm;                  // 64 x 128 (swizzled)
    float* sKV = sm + 64 * 128;       // 64 x 128 (K, then V; swizzled)
    float* sPd = sm + 2 * 64 * 128;   // 64 x 128: score at word 2c, then dup
    float* sM  = sm + 3 * 64 * 128;
    float* sL  = sM + 64;
    float* sAl = sL + 64;

    const int tid = threadIdx.x;
    const int q0 = blockIdx.x * 64;
    const int h = blockIdx.y, b = blockIdx.z;
    const size_t bh = (size_t)(b * HH + h) * SS * HDIM;
    const float* Qg = g_q + bh;
    const float* Kg = g_k + bh;
    const float* Vg = g_v + bh;
    const float* mbase = mask + (size_t)b * SS * SS;
    const float scale = 0.08838834764831845f;  // 128^-0.5

    const int rg = tid >> 4;          // 0..15 : score rows rg + 16*i
    const int cg = tid & 15;          // 0..15 : score cols cg + 16*j ; out dims cg*8..
    const int d0 = cg * 8;
    const int swzQ = (rg & 7) << 2;   // row-swizzle const for rows rg+16i
    const int swzK = (cg & 7) << 2;   // for rows cg+16j

    // load Q tile
    #pragma unroll
    for (int it = 0; it < 8; it++) {
        int idx = tid + it * 256;
        int r = idx >> 5, d4 = (idx & 31) * 4;
        *(float4*)&sQ[swz128(r, d4)] = *(const float4*)&Qg[(size_t)(q0 + r) * HDIM + d4];
    }
    if (tid < 64) { sM[tid] = -1e30f; sL[tid] = 0.0f; }

    u64 o2[4][4] = {};   // packed along d: (d0+2j2, d0+2j2+1)
    __syncthreads();

    for (int kt = 0; kt < 32; kt++) {
        const int k0 = kt * 64;
        // load K tile
        #pragma unroll
        for (int it = 0; it < 8; it++) {
            int idx = tid + it * 256;
            int r = idx >> 5, d4 = (idx & 31) * 4;
            *(float4*)&sKV[swz128(r, d4)] = *(const float4*)&Kg[(size_t)(k0 + r) * HDIM + d4];
        }
        __syncthreads();

        // Q K^T : packed along contraction d
        u64 acc[4][4] = {};
        #pragma unroll 8
        for (int d4 = 0; d4 < 128; d4 += 4) {
            ulonglong2 A[4], K[4];
            int xb = ((d4 >> 5) & 1) << 2;
            #pragma unroll
            for (int i = 0; i < 4; i++)
                A[i] = *(const ulonglong2*)&sQ[(rg + 16 * i) * 128 + (d4 ^ swzQ ^ xb)];
            #pragma unroll
            for (int j = 0; j < 4; j++)
                K[j] = *(const ulonglong2*)&sKV[(cg + 16 * j) * 128 + (d4 ^ swzK ^ xb)];
            #pragma unroll
            for (int i = 0; i < 4; i++)
                #pragma unroll
                for (int j = 0; j < 4; j++) {
                    acc[i][j] = fma2(A[i].x, K[j].x, acc[i][j]);
                    acc[i][j] = fma2(A[i].y, K[j].y, acc[i][j]);
                }
        }
        // scaled + masked scores -> even words of sPd
        #pragma unroll
        for (int i = 0; i < 4; i++) {
            int qr = rg + 16 * i;
            const float* mr = &mbase[(size_t)(q0 + qr) * SS + k0];
            #pragma unroll
            for (int j = 0; j < 4; j++) {
                int c = cg + 16 * j;
                sPd[qr * 128 + ((2 * c) ^ swzQ)] = f2sum(acc[i][j]) * scale + mr[c];
            }
        }
        __syncthreads();

        // online softmax: 4 threads per row, 16 cols each; write dup pairs
        {
            const int r = tid >> 2, sg = tid & 3;
            const int swzr = (r & 7) << 2;
            float sc[16];
            float mx = -1e30f;
            #pragma unroll
            for (int u = 0; u < 16; u++) {
                int c = sg * 16 + u;
                float2 t = *(const float2*)&sPd[r * 128 + ((2 * c) ^ swzr)];
                sc[u] = t.x;
                mx = fmaxf(mx, t.x);
            }
            mx = fmaxf(mx, __shfl_xor_sync(0xffffffffu, mx, 1));
            mx = fmaxf(mx, __shfl_xor_sync(0xffffffffu, mx, 2));
            float mo = sM[r];
            float mn = fmaxf(mo, mx);
            float al = __expf(mo - mn);
            float sum = 0.0f;
            #pragma unroll
            for (int u = 0; u < 16; u++) {
                sc[u] = __expf(sc[u] - mn);
                sum += sc[u];
            }
            #pragma unroll
            for (int u2 = 0; u2 < 8; u2++) {
                int c = sg * 16 + 2 * u2;
                float4 d = make_float4(sc[2 * u2], sc[2 * u2], sc[2 * u2 + 1], sc[2 * u2 + 1]);
                *(float4*)&sPd[r * 128 + ((2 * c) ^ swzr)] = d;
            }
            sum += __shfl_xor_sync(0xffffffffu, sum, 1);
            sum += __shfl_xor_sync(0xffffffffu, sum, 2);
            if (sg == 0) { sL[r] = sL[r] * al + sum; sM[r] = mn; sAl[r] = al; }
        }
        __syncthreads();

        // load V tile (same buffer as K)
        #pragma unroll
        for (int it = 0; it < 8; it++) {
            int idx = tid + it * 256;
            int r = idx >> 5, d4 = (idx & 31) * 4;
            *(float4*)&sKV[swz128(r, d4)] = *(const float4*)&Vg[(size_t)(k0 + r) * HDIM + d4];
        }
        __syncthreads();

        // rescale accumulators
        #pragma unroll
        for (int i = 0; i < 4; i++) {
            float a = sAl[rg + 16 * i];
            u64 a2 = pack2(a, a);
            #pragma unroll
            for (int j = 0; j < 4; j++) o2[i][j] = mul2(o2[i][j], a2);
        }

        // O += P * V : p read pre-packed (dup), v packed along d
        #pragma unroll 4
        for (int t2 = 0; t2 < 32; t2++) {
            ulonglong2 P[4];
            #pragma unroll
            for (int i = 0; i < 4; i++)
                P[i] = *(const ulonglong2*)&sPd[(rg + 16 * i) * 128 + ((4 * t2) ^ swzQ)];
            #pragma unroll
            for (int t = 0; t < 2; t++) {
                int tt = 2 * t2 + t;
                ulonglong2 V0 = *(const ulonglong2*)&sKV[swz128(tt, d0)];
                ulonglong2 V1 = *(const ulonglong2*)&sKV[swz128(tt, d0 + 4)];
                #pragma unroll
                for (int i = 0; i < 4; i++) {
                    u64 pv = t ? P[i].y : P[i].x;
                    o2[i][0] = fma2(pv, V0.x, o2[i][0]);
                    o2[i][1] = fma2(pv, V0.y, o2[i][1]);
                    o2[i][2] = fma2(pv, V1.x, o2[i][2]);
                    o2[i][3] = fma2(pv, V1.y, o2[i][3]);
                }
            }
        }
        __syncthreads();
    }

    // finalize
    #pragma unroll
    for (int i = 0; i < 4; i++) {
        int r = rg + 16 * i;
        float li = 1.0f / sL[r];
        float f[8];
        #pragma unroll
        for (int j = 0; j < 4; j++) f2unpack(o2[i][j], f[2 * j], f[2 * j + 1]);
        size_t ob = (size_t)(b * SS + q0 + r) * (HH * HDIM) + h * HDIM + d0;
        *(float4*)&g_attn[ob]     = make_float4(f[0] * li, f[1] * li, f[2] * li, f[3] * li);
        *(float4*)&g_attn[ob + 4] = make_float4(f[4] * li, f[5] * li, f[6] * li, f[7] * li);
    }
}

// ---------------------------------------------------------------------------
// Kernel 4a: output projection, split-K=4.  grid (64, 3, 4), block 256.
// ---------------------------------------------------------------------------
__global__ __launch_bounds__(256) void oproj_part_kernel(const float* __restrict__ wo)
{
    __shared__ __align__(16) float sA[64 * 32];
    __shared__ __align__(16) float sW[64 * 32];
    const int tid = threadIdx.x;
    const int m0 = blockIdx.x * 64;
    const int n0 = blockIdx.y * 64;
    const int kt = blockIdx.z;
    const int rg = tid >> 4, cg = tid & 15;
    const int r0 = rg * 4, c0 = cg * 4;
    const int swzA = (rg & 7) << 2;
    const int swzB = (cg & 7) << 2;
    u64 acc[4][4] = {};

    for (int kb = kt * 512; kb < kt * 512 + 512; kb += 32) {
        #pragma unroll
        for (int it = 0; it < 2; it++) {
            int idx = tid + it * 256;
            int r = idx >> 3, kq = (idx & 7) * 4;
            int sw = r * 32 + (kq ^ (((r >> 2) & 7) << 2));
            *(float4*)&sA[sw] = *(const float4*)&g_attn[(size_t)(m0 + r) * 2048 + kb + kq];
            *(float4*)&sW[sw] = *(const float4*)&wo[(size_t)(n0 + r) * 2048 + kb + kq];
        }
        __syncthreads();
        #pragma unroll
        for (int k4 = 0; k4 < 32; k4 += 4) {
            ulonglong2 A[4], B[4];
            #pragma unroll
            for (int i = 0; i < 4; i++)
                A[i] = *(const ulonglong2*)&sA[(r0 + i) * 32 + (k4 ^ swzA)];
            #pragma unroll
            for (int j = 0; j < 4; j++)
                B[j] = *(const ulonglong2*)&sW[(c0 + j) * 32 + (k4 ^ swzB)];
            #pragma unroll
            for (int i = 0; i < 4; i++)
                #pragma unroll
                for (int j = 0; j < 4; j++) {
                    acc[i][j] = fma2(A[i].x, B[j].x, acc[i][j]);
                    acc[i][j] = fma2(A[i].y, B[j].y, acc[i][j]);
                }
        }
        __syncthreads();
    }

    #pragma unroll
    for (int i = 0; i < 4; i++) {
        int m = m0 + r0 + i;
        int n = n0 + c0;
        if (n < DD) {
            float4 v = make_float4(f2sum(acc[i][0]), f2sum(acc[i][1]),
                                   f2sum(acc[i][2]), f2sum(acc[i][3]));
            *(float4*)&g_part[kt][(size_t)m * DD + n] = v;
        }
    }
}

// Kernel 4b: reduce the 4 split-K partials.  786432 floats = 196608 float4.
__global__ __launch_bounds__(256) void oproj_reduce_kernel(float* __restrict__ out)
{
    int idx = blockIdx.x * 256 + threadIdx.x;   // float4 index
    if (idx < (BB * SS * DD) / 4) {
        float4 a = *(const float4*)&g_part[0][idx * 4];
        float4 b = *(const float4*)&g_part[1][idx * 4];
        float4 c = *(const float4*)&g_part[2][idx * 4];
        float4 d = *(const float4*)&g_part[3][idx * 4];
        float4 r = make_float4(a.x + b.x + c.x + d.x, a.y + b.y + c.y + d.y,
                               a.z + b.z + c.z + d.z, a.w + b.w + c.w + d.w);
        *(float4*)&out[idx * 4] = r;
    }
}

// ---------------------------------------------------------------------------
// Inputs (metadata order): x, mask0, wq, wk, wv, wo, q_norm_w, k_norm_w
// ---------------------------------------------------------------------------
extern "C" void kernel_launch(void* const* d_in, const int* in_sizes, int n_in,
                              void* d_out, int out_size)
{
    const float* x     = (const float*)d_in[0];
    const float* mask0 = (const float*)d_in[1];
    const float* wq    = (const float*)d_in[2];
    const float* wk    = (const float*)d_in[3];
    const float* wv    = (const float*)d_in[4];
    const float* wo    = (const float*)d_in[5];
    const float* qnw   = (const float*)d_in[6];
    const float* knw   = (const float*)d_in[7];
    float* out = (float*)d_out;

    cudaFuncSetAttribute(attn_kernel, cudaFuncAttributeMaxDynamicSharedMemorySize,
                         AT_SMEM_BYTES);

    qkv_kernel<<<dim3(64, 32, 3), 256>>>(x, wq, wk, wv);
    normrope_kernel<<<BB * SS * HH, 128>>>(qnw, knw);
    attn_kernel<<<dim3(SS / 64, HH, BB), 256, AT_SMEM_BYTES>>>(mask0);
    oproj_part_kernel<<<dim3(64, 3, 4), 256>>>(wo);
    oproj_reduce_kernel<<<768, 256>>>(out);
}

// round 4
// speedup vs baseline: 1.9146x; 1.6760x over previous
// R4: attention on tensor cores (mma.sync m16n8k8 tf32). qkv/oproj stay FFMA2.
#include <cuda_runtime.h>
#include <cuda_bf16.h>
#include <math.h>
#include <stdint.h>
#include <stddef.h>

#define BB 2
#define SS 2048
#define DD 192
#define HH 16
#define HDIM 128

typedef unsigned long long u64;
typedef unsigned int u32;

// ---- packed f32x2 helpers (for qkv / oproj) ----
__device__ __forceinline__ u64 fma2(u64 a, u64 b, u64 c) {
    u64 d; asm("fma.rn.f32x2 %0, %1, %2, %3;" : "=l"(d) : "l"(a), "l"(b), "l"(c)); return d;
}
__device__ __forceinline__ float f2sum(u64 v) {
    float lo, hi; asm("mov.b64 {%0, %1}, %2;" : "=f"(lo), "=f"(hi) : "l"(v)); return lo + hi;
}

// ---- tf32 helpers ----
__device__ __forceinline__ u32 tf32r(float f) {
    u32 u; asm("cvt.rna.tf32.f32 %0, %1;" : "=r"(u) : "f"(f)); return u;
}
__device__ __forceinline__ void mma_tf32(float d[4], u32 a0, u32 a1, u32 a2, u32 a3,
                                         u32 b0, u32 b1) {
    asm volatile(
        "mma.sync.aligned.m16n8k8.row.col.f32.tf32.tf32.f32 "
        "{%0,%1,%2,%3}, {%4,%5,%6,%7}, {%8,%9}, {%0,%1,%2,%3};\n"
        : "+f"(d[0]), "+f"(d[1]), "+f"(d[2]), "+f"(d[3])
        : "r"(a0), "r"(a1), "r"(a2), "r"(a3), "r"(b0), "r"(b1));
}

// Scratch
__device__ float g_q[BB * HH * SS * HDIM];
__device__ float g_k[BB * HH * SS * HDIM];
__device__ float g_v[BB * HH * SS * HDIM];
__device__ float g_attn[BB * SS * HH * HDIM];
__device__ float g_part[4][BB * SS * DD];

// ---------------------------------------------------------------------------
// Kernel 1: QKV projection (FFMA2). grid (64, 32, 3), block 256.
// ---------------------------------------------------------------------------
__global__ __launch_bounds__(256) void qkv_kernel(
    const float* __restrict__ x,
    const float* __restrict__ wq,
    const float* __restrict__ wk,
    const float* __restrict__ wv)
{
    __shared__ __align__(16) float sA[64 * 32];
    __shared__ __align__(16) float sW[64 * 32];
    const int tid = threadIdx.x;
    const int m0 = blockIdx.x * 64;
    const int n0 = blockIdx.y * 64;
    const int z = blockIdx.z;
    const float* w = (z == 0) ? wq : (z == 1) ? wk : wv;
    float* dst = (z == 0) ? g_q : (z == 1) ? g_k : g_v;
    const int rg = tid >> 4, cg = tid & 15;
    const int r0 = rg * 4, c0 = cg * 4;
    const int swzA = (rg & 7) << 2;
    const int swzB = (cg & 7) << 2;
    u64 acc[4][4] = {};

    for (int kb = 0; kb < 192; kb += 32) {
        #pragma unroll
        for (int it = 0; it < 2; it++) {
            int idx = tid + it * 256;
            int r = idx >> 3, kq = (idx & 7) * 4;
            int sw = r * 32 + (kq ^ (((r >> 2) & 7) << 2));
            *(float4*)&sA[sw] = *(const float4*)&x[(size_t)(m0 + r) * 192 + kb + kq];
            *(float4*)&sW[sw] = *(const float4*)&w[(size_t)(n0 + r) * 192 + kb + kq];
        }
        __syncthreads();
        #pragma unroll
        for (int k4 = 0; k4 < 32; k4 += 4) {
            ulonglong2 A[4], B[4];
            #pragma unroll
            for (int i = 0; i < 4; i++)
                A[i] = *(const ulonglong2*)&sA[(r0 + i) * 32 + (k4 ^ swzA)];
            #pragma unroll
            for (int j = 0; j < 4; j++)
                B[j] = *(const ulonglong2*)&sW[(c0 + j) * 32 + (k4 ^ swzB)];
            #pragma unroll
            for (int i = 0; i < 4; i++)
                #pragma unroll
                for (int j = 0; j < 4; j++) {
                    acc[i][j] = fma2(A[i].x, B[j].x, acc[i][j]);
                    acc[i][j] = fma2(A[i].y, B[j].y, acc[i][j]);
                }
        }
        __syncthreads();
    }

    #pragma unroll
    for (int i = 0; i < 4; i++) {
        int m = m0 + r0 + i;
        int b = m >> 11, s = m & 2047;
        int n = n0 + c0;
        int h = n >> 7, hd = n & 127;
        float4 v = make_float4(f2sum(acc[i][0]), f2sum(acc[i][1]),
                               f2sum(acc[i][2]), f2sum(acc[i][3]));
        *(float4*)&dst[((size_t)(b * HH + h) * SS + s) * HDIM + hd] = v;
    }
}

// ---------------------------------------------------------------------------
// Kernel 2: per-head RMSNorm + RoPE, in place.
// ---------------------------------------------------------------------------
__global__ __launch_bounds__(128) void normrope_kernel(
    const float* __restrict__ qw, const float* __restrict__ kw)
{
    __shared__ float sq[128], sk[128], red[8];
    const int bs = blockIdx.x;
    const int h = bs & 15;
    const int s = (bs >> 4) & 2047;
    const int b = bs >> 15;
    const int hd = threadIdx.x;
    const size_t base = ((size_t)(b * HH + h) * SS + s) * HDIM;

    float qv = g_q[base + hd];
    float kv = g_k[base + hd];
    float q2 = qv * qv, k2 = kv * kv;
    #pragma unroll
    for (int off = 16; off; off >>= 1) {
        q2 += __shfl_xor_sync(0xffffffffu, q2, off);
        k2 += __shfl_xor_sync(0xffffffffu, k2, off);
    }
    if ((hd & 31) == 0) { red[hd >> 5] = q2; red[4 + (hd >> 5)] = k2; }
    __syncthreads();
    float qs = red[0] + red[1] + red[2] + red[3];
    float ks = red[4] + red[5] + red[6] + red[7];
    float qr = rsqrtf(qs * (1.0f / 128.0f) + 1e-6f);
    float kr = rsqrtf(ks * (1.0f / 128.0f) + 1e-6f);
    float qn = qv * qr * qw[hd];
    float kn = kv * kr * kw[hd];
    sq[hd] = qn; sk[hd] = kn;
    __syncthreads();

    int p = hd & 63;
    double inv = exp((double)p * -0.21586735246819178);  // -ln(1e6)/64
    double angd = fmod((double)s * inv, 6.283185307179586476925287);
    float ang = (float)angd;
    float sn = sinf(ang), cs = cosf(ang);
    float qrot = (hd < 64) ? -sq[hd + 64] : sq[hd - 64];
    float krot = (hd < 64) ? -sk[hd + 64] : sk[hd - 64];
    g_q[base + hd] = qn * cs + qrot * sn;
    g_k[base + hd] = kn * cs + krot * sn;
}

// ---------------------------------------------------------------------------
// Kernel 3: flash attention with tf32 mma.sync.  grid (32,16,2), block 256.
// 8 warps: QK^T -> 4 row-groups x 2 col-groups of the 64x64 score tile;
// PV -> 4 row-groups x 2 d-halves of the 64x128 output tile.
// smem strides: Q/K/V 132 (conflict-free fragments), P 68.
// ---------------------------------------------------------------------------
#define QKV_STRIDE 132
#define P_STRIDE 68
#define SQ_OFF 0
#define SKV_OFF (64 * QKV_STRIDE)                 // 8448
#define SP_OFF (2 * 64 * QKV_STRIDE)              // 16896
#define STAT_OFF (SP_OFF + 64 * P_STRIDE)         // 21248
#define AT_SMEM_FLOATS (STAT_OFF + 384)
#define AT_SMEM_BYTES (AT_SMEM_FLOATS * 4)        // 86528

__global__ __launch_bounds__(256, 2) void attn_kernel(const float* __restrict__ mask)
{
    extern __shared__ __align__(16) u32 smu[];
    u32* sQ = smu + SQ_OFF;
    u32* sKV = smu + SKV_OFF;
    u32* sP = smu + SP_OFF;
    float* sRmax = (float*)(smu + STAT_OFF);      // [2][64]
    float* sRsum = sRmax + 128;                   // [2][64]
    float* sM = sRsum + 128;                      // [64]
    float* sL = sM + 64;                          // [64]

    const int tid = threadIdx.x;
    const int wid = tid >> 5;
    const int lane = tid & 31;
    const int g = lane >> 2;            // group id 0..7
    const int q4 = lane & 3;            // quad lane 0..3
    const int rw = wid & 3;             // row group: rows rw*16 .. +16
    const int cw = wid >> 2;            // col group (QK: cols cw*32; PV: d cw*64)

    const int q0 = blockIdx.x * 64;
    const int h = blockIdx.y, b = blockIdx.z;
    const size_t bh = (size_t)(b * HH + h) * SS * HDIM;
    const float* Qg = g_q + bh;
    const float* Kg = g_k + bh;
    const float* Vg = g_v + bh;
    const float* mbase = mask + (size_t)b * SS * SS;
    const float scale = 0.08838834764831845f;

    const int R0 = rw * 16 + g;
    const int R1 = R0 + 8;

    // load Q tile (tf32-rounded)
    #pragma unroll
    for (int it = 0; it < 8; it++) {
        int idx = tid + it * 256;
        int r = idx >> 5, c4 = (idx & 31) * 4;
        float4 v = *(const float4*)&Qg[(size_t)(q0 + r) * HDIM + c4];
        uint4 u = make_uint4(tf32r(v.x), tf32r(v.y), tf32r(v.z), tf32r(v.w));
        *(uint4*)&sQ[r * QKV_STRIDE + c4] = u;
    }
    if (tid < 64) { sM[tid] = -1e30f; sL[tid] = 0.0f; }

    float Od[8][4];
    #pragma unroll
    for (int n = 0; n < 8; n++)
        #pragma unroll
        for (int k = 0; k < 4; k++) Od[n][k] = 0.0f;

    __syncthreads();

    for (int kt = 0; kt < 32; kt++) {
        const int k0 = kt * 64;
        // load K tile
        #pragma unroll
        for (int it = 0; it < 8; it++) {
            int idx = tid + it * 256;
            int r = idx >> 5, c4 = (idx & 31) * 4;
            float4 v = *(const float4*)&Kg[(size_t)(k0 + r) * HDIM + c4];
            uint4 u = make_uint4(tf32r(v.x), tf32r(v.y), tf32r(v.z), tf32r(v.w));
            *(uint4*)&sKV[r * QKV_STRIDE + c4] = u;
        }
        __syncthreads();

        // ---- QK^T: warp computes rows rw*16..+16, cols cw*32..+32 ----
        float acc[4][4];
        #pragma unroll
        for (int n = 0; n < 4; n++)
            #pragma unroll
            for (int k = 0; k < 4; k++) acc[n][k] = 0.0f;

        #pragma unroll
        for (int kk = 0; kk < 128; kk += 8) {
            u32 a0 = sQ[(rw * 16 + g) * QKV_STRIDE + kk + q4];
            u32 a1 = sQ[(rw * 16 + g + 8) * QKV_STRIDE + kk + q4];
            u32 a2 = sQ[(rw * 16 + g) * QKV_STRIDE + kk + q4 + 4];
            u32 a3 = sQ[(rw * 16 + g + 8) * QKV_STRIDE + kk + q4 + 4];
            #pragma unroll
            for (int nt = 0; nt < 4; nt++) {
                int cn = cw * 32 + nt * 8 + g;
                u32 b0 = sKV[cn * QKV_STRIDE + kk + q4];
                u32 b1 = sKV[cn * QKV_STRIDE + kk + q4 + 4];
                mma_tf32(acc[nt], a0, a1, a2, a3, b0, b1);
            }
        }

        // ---- scale + mask, row max ----
        const float* mr0 = &mbase[(size_t)(q0 + R0) * SS + k0];
        const float* mr1 = &mbase[(size_t)(q0 + R1) * SS + k0];
        float mx0 = -1e30f, mx1 = -1e30f;
        #pragma unroll
        for (int nt = 0; nt < 4; nt++) {
            int c = cw * 32 + nt * 8 + 2 * q4;
            acc[nt][0] = acc[nt][0] * scale + mr0[c];
            acc[nt][1] = acc[nt][1] * scale + mr0[c + 1];
            acc[nt][2] = acc[nt][2] * scale + mr1[c];
            acc[nt][3] = acc[nt][3] * scale + mr1[c + 1];
            mx0 = fmaxf(mx0, fmaxf(acc[nt][0], acc[nt][1]));
            mx1 = fmaxf(mx1, fmaxf(acc[nt][2], acc[nt][3]));
        }
        mx0 = fmaxf(mx0, __shfl_xor_sync(0xffffffffu, mx0, 1));
        mx0 = fmaxf(mx0, __shfl_xor_sync(0xffffffffu, mx0, 2));
        mx1 = fmaxf(mx1, __shfl_xor_sync(0xffffffffu, mx1, 1));
        mx1 = fmaxf(mx1, __shfl_xor_sync(0xffffffffu, mx1, 2));
        if (q4 == 0) { sRmax[cw * 64 + R0] = mx0; sRmax[cw * 64 + R1] = mx1; }
        __syncthreads();   // S1: maxes visible; all smem MMA reads done

        // ---- combine maxes, exp, partial sums, write P, rescale O ----
        float mn0 = fmaxf(sM[R0], fmaxf(sRmax[R0], sRmax[64 + R0]));
        float mn1 = fmaxf(sM[R1], fmaxf(sRmax[R1], sRmax[64 + R1]));
        float al0 = __expf(sM[R0] - mn0);
        float al1 = __expf(sM[R1] - mn1);
        float sum0 = 0.0f, sum1 = 0.0f;
        #pragma unroll
        for (int nt = 0; nt < 4; nt++) {
            int c = cw * 32 + nt * 8 + 2 * q4;
            float e0 = __expf(acc[nt][0] - mn0);
            float e1 = __expf(acc[nt][1] - mn0);
            float e2 = __expf(acc[nt][2] - mn1);
            float e3 = __expf(acc[nt][3] - mn1);
            sum0 += e0 + e1; sum1 += e2 + e3;
            sP[R0 * P_STRIDE + c] = tf32r(e0);
            sP[R0 * P_STRIDE + c + 1] = tf32r(e1);
            sP[R1 * P_STRIDE + c] = tf32r(e2);
            sP[R1 * P_STRIDE + c + 1] = tf32r(e3);
        }
        sum0 += __shfl_xor_sync(0xffffffffu, sum0, 1);
        sum0 += __shfl_xor_sync(0xffffffffu, sum0, 2);
        sum1 += __shfl_xor_sync(0xffffffffu, sum1, 1);
        sum1 += __shfl_xor_sync(0xffffffffu, sum1, 2);
        if (q4 == 0) { sRsum[cw * 64 + R0] = sum0; sRsum[cw * 64 + R1] = sum1; }
        #pragma unroll
        for (int n = 0; n < 8; n++) {
            Od[n][0] *= al0; Od[n][1] *= al0;
            Od[n][2] *= al1; Od[n][3] *= al1;
        }
        // load V tile (overwrites K; K reads finished at S1)
        #pragma unroll
        for (int it = 0; it < 8; it++) {
            int idx = tid + it * 256;
            int r = idx >> 5, c4 = (idx & 31) * 4;
            float4 v = *(const float4*)&Vg[(size_t)(k0 + r) * HDIM + c4];
            uint4 u = make_uint4(tf32r(v.x), tf32r(v.y), tf32r(v.z), tf32r(v.w));
            *(uint4*)&sKV[r * QKV_STRIDE + c4] = u;
        }
        __syncthreads();   // S2: P, V, partial sums ready

        // stats update (single writer per row)
        if (cw == 0 && q4 == 0) {
            sL[R0] = sL[R0] * al0 + sRsum[R0] + sRsum[64 + R0];
            sL[R1] = sL[R1] * al1 + sRsum[R1] + sRsum[64 + R1];
            sM[R0] = mn0; sM[R1] = mn1;
        }

        // ---- PV: warp computes rows rw*16..+16, d cols cw*64..+64 ----
        #pragma unroll
        for (int tk = 0; tk < 64; tk += 8) {
            u32 a0 = sP[(rw * 16 + g) * P_STRIDE + tk + q4];
            u32 a1 = sP[(rw * 16 + g + 8) * P_STRIDE + tk + q4];
            u32 a2 = sP[(rw * 16 + g) * P_STRIDE + tk + q4 + 4];
            u32 a3 = sP[(rw * 16 + g + 8) * P_STRIDE + tk + q4 + 4];
            #pragma unroll
            for (int nt = 0; nt < 8; nt++) {
                int dc = cw * 64 + nt * 8 + g;
                u32 b0 = sKV[(tk + q4) * QKV_STRIDE + dc];
                u32 b1 = sKV[(tk + q4 + 4) * QKV_STRIDE + dc];
                mma_tf32(Od[nt], a0, a1, a2, a3, b0, b1);
            }
        }
        __syncthreads();   // S3: PV reads done; stats written before next read
    }

    // ---- finalize: divide by denom, write out ----
    float li0 = 1.0f / sL[R0];
    float li1 = 1.0f / sL[R1];
    #pragma unroll
    for (int nt = 0; nt < 8; nt++) {
        int dc = cw * 64 + nt * 8 + 2 * q4;
        size_t ob0 = (size_t)(b * SS + q0 + R0) * (HH * HDIM) + h * HDIM + dc;
        size_t ob1 = (size_t)(b * SS + q0 + R1) * (HH * HDIM) + h * HDIM + dc;
        *(float2*)&g_attn[ob0] = make_float2(Od[nt][0] * li0, Od[nt][1] * li0);
        *(float2*)&g_attn[ob1] = make_float2(Od[nt][2] * li1, Od[nt][3] * li1);
    }
}

// ---------------------------------------------------------------------------
// Kernel 4a: output projection, split-K=4 (FFMA2). grid (64, 3, 4), block 256.
// ---------------------------------------------------------------------------
__global__ __launch_bounds__(256) void oproj_part_kernel(const float* __restrict__ wo)
{
    __shared__ __align__(16) float sA[64 * 32];
    __shared__ __align__(16) float sW[64 * 32];
    const int tid = threadIdx.x;
    const int m0 = blockIdx.x * 64;
    const int n0 = blockIdx.y * 64;
    const int kt = blockIdx.z;
    const int rg = tid >> 4, cg = tid & 15;
    const int r0 = rg * 4, c0 = cg * 4;
    const int swzA = (rg & 7) << 2;
    const int swzB = (cg & 7) << 2;
    u64 acc[4][4] = {};

    for (int kb = kt * 512; kb < kt * 512 + 512; kb += 32) {
        #pragma unroll
        for (int it = 0; it < 2; it++) {
            int idx = tid + it * 256;
            int r = idx >> 3, kq = (idx & 7) * 4;
            int sw = r * 32 + (kq ^ (((r >> 2) & 7) << 2));
            *(float4*)&sA[sw] = *(const float4*)&g_attn[(size_t)(m0 + r) * 2048 + kb + kq];
            *(float4*)&sW[sw] = *(const float4*)&wo[(size_t)(n0 + r) * 2048 + kb + kq];
        }
        __syncthreads();
        #pragma unroll
        for (int k4 = 0; k4 < 32; k4 += 4) {
            ulonglong2 A[4], B[4];
            #pragma unroll
            for (int i = 0; i < 4; i++)
                A[i] = *(const ulonglong2*)&sA[(r0 + i) * 32 + (k4 ^ swzA)];
            #pragma unroll
            for (int j = 0; j < 4; j++)
                B[j] = *(const ulonglong2*)&sW[(c0 + j) * 32 + (k4 ^ swzB)];
            #pragma unroll
            for (int i = 0; i < 4; i++)
                #pragma unroll
                for (int j = 0; j < 4; j++) {
                    acc[i][j] = fma2(A[i].x, B[j].x, acc[i][j]);
                    acc[i][j] = fma2(A[i].y, B[j].y, acc[i][j]);
                }
        }
        __syncthreads();
    }

    #pragma unroll
    for (int i = 0; i < 4; i++) {
        int m = m0 + r0 + i;
        int n = n0 + c0;
        if (n < DD) {
            float4 v = make_float4(f2sum(acc[i][0]), f2sum(acc[i][1]),
                                   f2sum(acc[i][2]), f2sum(acc[i][3]));
            *(float4*)&g_part[kt][(size_t)m * DD + n] = v;
        }
    }
}

__global__ __launch_bounds__(256) void oproj_reduce_kernel(float* __restrict__ out)
{
    int idx = blockIdx.x * 256 + threadIdx.x;
    if (idx < (BB * SS * DD) / 4) {
        float4 a = *(const float4*)&g_part[0][idx * 4];
        float4 b = *(const float4*)&g_part[1][idx * 4];
        float4 c = *(const float4*)&g_part[2][idx * 4];
        float4 d = *(const float4*)&g_part[3][idx * 4];
        float4 r = make_float4(a.x + b.x + c.x + d.x, a.y + b.y + c.y + d.y,
                               a.z + b.z + c.z + d.z, a.w + b.w + c.w + d.w);
        *(float4*)&out[idx * 4] = r;
    }
}

// ---------------------------------------------------------------------------
// Inputs: x, mask0, wq, wk, wv, wo, q_norm_w, k_norm_w
// ---------------------------------------------------------------------------
extern "C" void kernel_launch(void* const* d_in, const int* in_sizes, int n_in,
                              void* d_out, int out_size)
{
    const float* x     = (const float*)d_in[0];
    const float* mask0 = (const float*)d_in[1];
    const float* wq    = (const float*)d_in[2];
    const float* wk    = (const float*)d_in[3];
    const float* wv    = (const float*)d_in[4];
    const float* wo    = (const float*)d_in[5];
    const float* qnw   = (const float*)d_in[6];
    const float* knw   = (const float*)d_in[7];
    float* out = (float*)d_out;

    cudaFuncSetAttribute(attn_kernel, cudaFuncAttributeMaxDynamicSharedMemorySize,
                         AT_SMEM_BYTES);

    qkv_kernel<<<dim3(64, 32, 3), 256>>>(x, wq, wk, wv);
    normrope_kernel<<<BB * SS * HH, 128>>>(qnw, knw);
    attn_kernel<<<dim3(SS / 64, HH, BB), 256, AT_SMEM_BYTES>>>(mask0);
    oproj_part_kernel<<<dim3(64, 3, 4), 256>>>(wo);
    oproj_reduce_kernel<<<768, 256>>>(out);
}

// round 6
// speedup vs baseline: 2.4059x; 1.2566x over previous
// R6: attention via legacy mma.sync m16n8k16 fp16 (tcgen05 unavailable: harness
// PTX targets compute_103 without the 'a' feature suffix). Register-resident Q,
// max-free softmax in exp2 domain, conflict-free padded smem.
#include <cuda_runtime.h>
#include <cuda_fp16.h>
#include <math.h>
#include <stdint.h>
#include <stddef.h>

#define BB 2
#define SS 2048
#define DD 192
#define HH 16
#define HDIM 128

typedef unsigned long long u64;
typedef unsigned int u32;

// ---- packed f32x2 helpers (qkv / oproj) ----
__device__ __forceinline__ u64 fma2(u64 a, u64 b, u64 c) {
    u64 d; asm("fma.rn.f32x2 %0, %1, %2, %3;" : "=l"(d) : "l"(a), "l"(b), "l"(c)); return d;
}
__device__ __forceinline__ float f2sum(u64 v) {
    float lo, hi; asm("mov.b64 {%0, %1}, %2;" : "=f"(lo), "=f"(hi) : "l"(v)); return lo + hi;
}

// ---- fp16 helpers ----
__device__ __forceinline__ u32 h2(float a, float b) {
    __half2 h = __floats2half2_rn(a, b);
    return *(u32*)&h;
}
__device__ __forceinline__ void mma_f16(float d[4], u32 a0, u32 a1, u32 a2, u32 a3,
                                        u32 b0, u32 b1) {
    asm volatile(
        "mma.sync.aligned.m16n8k16.row.col.f32.f16.f16.f32 "
        "{%0,%1,%2,%3}, {%4,%5,%6,%7}, {%8,%9}, {%0,%1,%2,%3};\n"
        : "+f"(d[0]), "+f"(d[1]), "+f"(d[2]), "+f"(d[3])
        : "r"(a0), "r"(a1), "r"(a2), "r"(a3), "r"(b0), "r"(b1));
}

// Scratch
__device__ float g_q[BB * HH * SS * HDIM];
__device__ float g_k[BB * HH * SS * HDIM];
__device__ float g_v[BB * HH * SS * HDIM];
__device__ float g_attn[BB * SS * HH * HDIM];
__device__ float g_part[4][BB * SS * DD];

// ---------------------------------------------------------------------------
// Kernel 1: QKV projection (FFMA2). grid (64, 32, 3), block 256.
// ---------------------------------------------------------------------------
__global__ __launch_bounds__(256) void qkv_kernel(
    const float* __restrict__ x, const float* __restrict__ wq,
    const float* __restrict__ wk, const float* __restrict__ wv)
{
    __shared__ __align__(16) float sA[64 * 32];
    __shared__ __align__(16) float sW[64 * 32];
    const int tid = threadIdx.x;
    const int m0 = blockIdx.x * 64;
    const int n0 = blockIdx.y * 64;
    const int z = blockIdx.z;
    const float* w = (z == 0) ? wq : (z == 1) ? wk : wv;
    float* dst = (z == 0) ? g_q : (z == 1) ? g_k : g_v;
    const int rg = tid >> 4, cg = tid & 15;
    const int r0 = rg * 4, c0 = cg * 4;
    const int swzA = (rg & 7) << 2, swzB = (cg & 7) << 2;
    u64 acc[4][4] = {};

    for (int kb = 0; kb < 192; kb += 32) {
        #pragma unroll
        for (int it = 0; it < 2; it++) {
            int idx = tid + it * 256;
            int r = idx >> 3, kq = (idx & 7) * 4;
            int sw = r * 32 + (kq ^ (((r >> 2) & 7) << 2));
            *(float4*)&sA[sw] = *(const float4*)&x[(size_t)(m0 + r) * 192 + kb + kq];
            *(float4*)&sW[sw] = *(const float4*)&w[(size_t)(n0 + r) * 192 + kb + kq];
        }
        __syncthreads();
        #pragma unroll
        for (int k4 = 0; k4 < 32; k4 += 4) {
            ulonglong2 A[4], B[4];
            #pragma unroll
            for (int i = 0; i < 4; i++) A[i] = *(const ulonglong2*)&sA[(r0 + i) * 32 + (k4 ^ swzA)];
            #pragma unroll
            for (int j = 0; j < 4; j++) B[j] = *(const ulonglong2*)&sW[(c0 + j) * 32 + (k4 ^ swzB)];
            #pragma unroll
            for (int i = 0; i < 4; i++)
                #pragma unroll
                for (int j = 0; j < 4; j++) {
                    acc[i][j] = fma2(A[i].x, B[j].x, acc[i][j]);
                    acc[i][j] = fma2(A[i].y, B[j].y, acc[i][j]);
                }
        }
        __syncthreads();
    }
    #pragma unroll
    for (int i = 0; i < 4; i++) {
        int m = m0 + r0 + i;
        int b = m >> 11, s = m & 2047;
        int n = n0 + c0;
        int h = n >> 7, hd = n & 127;
        float4 v = make_float4(f2sum(acc[i][0]), f2sum(acc[i][1]), f2sum(acc[i][2]), f2sum(acc[i][3]));
        *(float4*)&dst[((size_t)(b * HH + h) * SS + s) * HDIM + hd] = v;
    }
}

// ---------------------------------------------------------------------------
// Kernel 2: per-head RMSNorm + RoPE, in place.
// ---------------------------------------------------------------------------
__global__ __launch_bounds__(128) void normrope_kernel(
    const float* __restrict__ qw, const float* __restrict__ kw)
{
    __shared__ float sq[128], sk[128], red[8];
    const int bs = blockIdx.x;
    const int h = bs & 15;
    const int s = (bs >> 4) & 2047;
    const int b = bs >> 15;
    const int hd = threadIdx.x;
    const size_t base = ((size_t)(b * HH + h) * SS + s) * HDIM;

    float qv = g_q[base + hd];
    float kv = g_k[base + hd];
    float q2 = qv * qv, k2 = kv * kv;
    #pragma unroll
    for (int off = 16; off; off >>= 1) {
        q2 += __shfl_xor_sync(0xffffffffu, q2, off);
        k2 += __shfl_xor_sync(0xffffffffu, k2, off);
    }
    if ((hd & 31) == 0) { red[hd >> 5] = q2; red[4 + (hd >> 5)] = k2; }
    __syncthreads();
    float qs = red[0] + red[1] + red[2] + red[3];
    float ks = red[4] + red[5] + red[6] + red[7];
    float qr = rsqrtf(qs * (1.0f / 128.0f) + 1e-6f);
    float kr = rsqrtf(ks * (1.0f / 128.0f) + 1e-6f);
    float qn = qv * qr * qw[hd];
    float kn = kv * kr * kw[hd];
    sq[hd] = qn; sk[hd] = kn;
    __syncthreads();

    int p = hd & 63;
    double inv = exp((double)p * -0.21586735246819178);
    double angd = fmod((double)s * inv, 6.283185307179586476925287);
    float ang = (float)angd;
    float sn = sinf(ang), cs = cosf(ang);
    float qrot = (hd < 64) ? -sq[hd + 64] : sq[hd - 64];
    float krot = (hd < 64) ? -sk[hd + 64] : sk[hd - 64];
    g_q[base + hd] = qn * cs + qrot * sn;
    g_k[base + hd] = kn * cs + krot * sn;
}

// ---------------------------------------------------------------------------
// Kernel 3: flash attention, fp16 mma. grid (16, 16, 2), block 256 (8 warps).
// Warp (rw = wid&3, cw = wid>>2):
//   QK: rows [32rw,+32) x key cols [32cw,+32); PV: rows x d [64cw,+64).
// Q fragments live in registers for all 32 key tiles.
// smem u32 arrays: sK[64][68] (key, d-pairs), sV[128][36] (d, key-pairs,
// transposed at load), sP[128][36] (row, key-pairs). All fragment LDS
// conflict-free: bank = 4g + q patterns.
// Softmax: max-free, exp2-domain (log2e folded into Q scale), offset 4.
// ---------------------------------------------------------------------------
#define SKB 0
#define SVB 17408
#define SPB 35840
#define SLB 54272
#define AT_SMEM (SLB + 1024)

#define QSCALE (0.08838834764831845f * 1.4426950408889634f)
#define LOG2E 1.4426950408889634f
#define EOFF (4.0f * 1.4426950408889634f)

__global__ __launch_bounds__(256, 1) void attn_kernel(const float* __restrict__ mask)
{
    extern __shared__ __align__(16) char smc[];
    u32* sK = (u32*)(smc + SKB);
    u32* sV = (u32*)(smc + SVB);
    u32* sP = (u32*)(smc + SPB);
    float* sL = (float*)(smc + SLB);   // [2][128] per-col-group row sums

    const int tid = threadIdx.x;
    const int wid = tid >> 5, lane = tid & 31;
    const int g = lane >> 2, q4 = lane & 3;
    const int rw = wid & 3, cw = wid >> 2;

    const int q0 = blockIdx.x * 128;
    const int h = blockIdx.y, b = blockIdx.z;
    const size_t bh = (size_t)(b * HH + h) * SS * HDIM;
    const float* Qg = g_q + bh;
    const float* Kg = g_k + bh;
    const float* Vg = g_v + bh;
    const float* mbase = mask + (size_t)b * SS * SS;

    // ---- Q fragments -> registers (scaled by QSCALE, fp16) ----
    u32 qf[2][8][4];
    #pragma unroll
    for (int mt = 0; mt < 2; mt++)
        #pragma unroll
        for (int kk = 0; kk < 8; kk++) {
            const float* qp = &Qg[(size_t)(q0 + 32 * rw + 16 * mt + g) * HDIM + 2 * q4 + 16 * kk];
            float2 v0 = *(const float2*)qp;
            float2 v1 = *(const float2*)(qp + 8 * HDIM);
            float2 v2 = *(const float2*)(qp + 8);
            float2 v3 = *(const float2*)(qp + 8 * HDIM + 8);
            qf[mt][kk][0] = h2(v0.x * QSCALE, v0.y * QSCALE);
            qf[mt][kk][1] = h2(v1.x * QSCALE, v1.y * QSCALE);
            qf[mt][kk][2] = h2(v2.x * QSCALE, v2.y * QSCALE);
            qf[mt][kk][3] = h2(v3.x * QSCALE, v3.y * QSCALE);
        }

    float o[2][8][4];
    #pragma unroll
    for (int mt = 0; mt < 2; mt++)
        #pragma unroll
        for (int nt = 0; nt < 8; nt++)
            #pragma unroll
            for (int c = 0; c < 4; c++) o[mt][nt][c] = 0.0f;
    float rsum[2][2] = {};

    for (int kt = 0; kt < 32; kt++) {
        const int k0 = kt * 64;
        __syncthreads();   // previous tile's MMA reads done; safe to overwrite

        // K: [key][d-pairs], coalesced rows
        #pragma unroll
        for (int it = 0; it < 8; it++) {
            int idx = tid + it * 256;
            int l = idx & 31, t = idx >> 5;
            float4 v = *(const float4*)&Kg[(size_t)(k0 + t) * HDIM + 4 * l];
            sK[t * 68 + 2 * l] = h2(v.x, v.y);
            sK[t * 68 + 2 * l + 1] = h2(v.z, v.w);
        }
        // V transposed: [d][key-pairs]
        #pragma unroll
        for (int it = 0; it < 4; it++) {
            int idx = tid + it * 256;
            int l = idx & 31, t = idx >> 5;
            const float* va = &Vg[(size_t)(k0 + 2 * t) * HDIM + 4 * l];
            float4 A4 = *(const float4*)va;
            float4 B4 = *(const float4*)(va + HDIM);
            sV[(4 * l + 0) * 36 + t] = h2(A4.x, B4.x);
            sV[(4 * l + 1) * 36 + t] = h2(A4.y, B4.y);
            sV[(4 * l + 2) * 36 + t] = h2(A4.z, B4.z);
            sV[(4 * l + 3) * 36 + t] = h2(A4.w, B4.w);
        }
        __syncthreads();

        // ---- QK^T (A = registers, B = sK) ----
        float acc[2][4][4];
        #pragma unroll
        for (int mt = 0; mt < 2; mt++)
            #pragma unroll
            for (int nt = 0; nt < 4; nt++)
                #pragma unroll
                for (int c = 0; c < 4; c++) acc[mt][nt][c] = 0.0f;
        #pragma unroll
        for (int kk = 0; kk < 8; kk++) {
            #pragma unroll
            for (int nt = 0; nt < 4; nt++) {
                int key = 32 * cw + 8 * nt + g;
                u32 b0 = sK[key * 68 + 8 * kk + q4];
                u32 b1 = sK[key * 68 + 8 * kk + q4 + 4];
                mma_f16(acc[0][nt], qf[0][kk][0], qf[0][kk][1], qf[0][kk][2], qf[0][kk][3], b0, b1);
                mma_f16(acc[1][nt], qf[1][kk][0], qf[1][kk][1], qf[1][kk][2], qf[1][kk][3], b0, b1);
            }
        }

        // ---- softmax epilogue: exp2(acc + mask*log2e - EOFF) -> sP fp16 ----
        #pragma unroll
        for (int mt = 0; mt < 2; mt++) {
            int row0 = 32 * rw + 16 * mt + g;
            #pragma unroll
            for (int nt = 0; nt < 4; nt++) {
                const float* mp = &mbase[(size_t)(q0 + row0) * SS + k0 + 32 * cw + 8 * nt + 2 * q4];
                float2 m0 = *(const float2*)mp;
                float2 m1 = *(const float2*)(mp + 8 * SS);
                float e0 = exp2f(acc[mt][nt][0] + m0.x * LOG2E - EOFF);
                float e1 = exp2f(acc[mt][nt][1] + m0.y * LOG2E - EOFF);
                float e2 = exp2f(acc[mt][nt][2] + m1.x * LOG2E - EOFF);
                float e3 = exp2f(acc[mt][nt][3] + m1.y * LOG2E - EOFF);
                rsum[mt][0] += e0 + e1;
                rsum[mt][1] += e2 + e3;
                sP[row0 * 36 + 16 * cw + 4 * nt + q4] = h2(e0, e1);
                sP[(row0 + 8) * 36 + 16 * cw + 4 * nt + q4] = h2(e2, e3);
            }
        }
        __syncthreads();

        // ---- PV (A = sP, B = sV) ----
        #pragma unroll
        for (int kk = 0; kk < 4; kk++) {
            u32 a[2][4];
            #pragma unroll
            for (int mt = 0; mt < 2; mt++) {
                int row0 = 32 * rw + 16 * mt + g;
                a[mt][0] = sP[row0 * 36 + q4 + 8 * kk];
                a[mt][1] = sP[(row0 + 8) * 36 + q4 + 8 * kk];
                a[mt][2] = sP[row0 * 36 + q4 + 4 + 8 * kk];
                a[mt][3] = sP[(row0 + 8) * 36 + q4 + 4 + 8 * kk];
            }
            #pragma unroll
            for (int nt = 0; nt < 8; nt++) {
                int d = 64 * cw + 8 * nt + g;
                u32 b0 = sV[d * 36 + q4 + 8 * kk];
                u32 b1 = sV[d * 36 + q4 + 4 + 8 * kk];
                mma_f16(o[0][nt], a[0][0], a[0][1], a[0][2], a[0][3], b0, b1);
                mma_f16(o[1][nt], a[1][0], a[1][1], a[1][2], a[1][3], b0, b1);
            }
        }
    }

    // ---- finalize ----
    #pragma unroll
    for (int mt = 0; mt < 2; mt++)
        #pragma unroll
        for (int half = 0; half < 2; half++) {
            float s = rsum[mt][half];
            s += __shfl_xor_sync(0xffffffffu, s, 1);
            s += __shfl_xor_sync(0xffffffffu, s, 2);
            rsum[mt][half] = s;
        }
    if (q4 == 0) {
        #pragma unroll
        for (int mt = 0; mt < 2; mt++) {
            sL[cw * 128 + 32 * rw + 16 * mt + g] = rsum[mt][0];
            sL[cw * 128 + 32 * rw + 16 * mt + g + 8] = rsum[mt][1];
        }
    }
    __syncthreads();

    #pragma unroll
    for (int mt = 0; mt < 2; mt++) {
        int row0 = 32 * rw + 16 * mt + g;
        float inv0 = 1.0f / (sL[row0] + sL[128 + row0]);
        float inv1 = 1.0f / (sL[row0 + 8] + sL[128 + row0 + 8]);
        #pragma unroll
        for (int nt = 0; nt < 8; nt++) {
            int d = 64 * cw + 8 * nt + 2 * q4;
            size_t ob0 = (size_t)(b * SS + q0 + row0) * (HH * HDIM) + h * HDIM + d;
            size_t ob1 = (size_t)(b * SS + q0 + row0 + 8) * (HH * HDIM) + h * HDIM + d;
            *(float2*)&g_attn[ob0] = make_float2(o[mt][nt][0] * inv0, o[mt][nt][1] * inv0);
            *(float2*)&g_attn[ob1] = make_float2(o[mt][nt][2] * inv1, o[mt][nt][3] * inv1);
        }
    }
}

// ---------------------------------------------------------------------------
// Kernel 4a/4b: output projection split-K=4 (FFMA2) + reduce.
// ---------------------------------------------------------------------------
__global__ __launch_bounds__(256) void oproj_part_kernel(const float* __restrict__ wo)
{
    __shared__ __align__(16) float sA[64 * 32];
    __shared__ __align__(16) float sW[64 * 32];
    const int tid = threadIdx.x;
    const int m0 = blockIdx.x * 64;
    const int n0 = blockIdx.y * 64;
    const int kt = blockIdx.z;
    const int rg = tid >> 4, cg = tid & 15;
    const int r0 = rg * 4, c0 = cg * 4;
    const int swzA = (rg & 7) << 2, swzB = (cg & 7) << 2;
    u64 acc[4][4] = {};

    for (int kb = kt * 512; kb < kt * 512 + 512; kb += 32) {
        #pragma unroll
        for (int it = 0; it < 2; it++) {
            int idx = tid + it * 256;
            int r = idx >> 3, kq = (idx & 7) * 4;
            int sw = r * 32 + (kq ^ (((r >> 2) & 7) << 2));
            *(float4*)&sA[sw] = *(const float4*)&g_attn[(size_t)(m0 + r) * 2048 + kb + kq];
            *(float4*)&sW[sw] = *(const float4*)&wo[(size_t)(n0 + r) * 2048 + kb + kq];
        }
        __syncthreads();
        #pragma unroll
        for (int k4 = 0; k4 < 32; k4 += 4) {
            ulonglong2 A[4], B[4];
            #pragma unroll
            for (int i = 0; i < 4; i++) A[i] = *(const ulonglong2*)&sA[(r0 + i) * 32 + (k4 ^ swzA)];
            #pragma unroll
            for (int j = 0; j < 4; j++) B[j] = *(const ulonglong2*)&sW[(c0 + j) * 32 + (k4 ^ swzB)];
            #pragma unroll
            for (int i = 0; i < 4; i++)
                #pragma unroll
                for (int j = 0; j < 4; j++) {
                    acc[i][j] = fma2(A[i].x, B[j].x, acc[i][j]);
                    acc[i][j] = fma2(A[i].y, B[j].y, acc[i][j]);
                }
        }
        __syncthreads();
    }
    #pragma unroll
    for (int i = 0; i < 4; i++) {
        int m = m0 + r0 + i;
        int n = n0 + c0;
        if (n < DD) {
            float4 v = make_float4(f2sum(acc[i][0]), f2sum(acc[i][1]), f2sum(acc[i][2]), f2sum(acc[i][3]));
            *(float4*)&g_part[kt][(size_t)m * DD + n] = v;
        }
    }
}

__global__ __launch_bounds__(256) void oproj_reduce_kernel(float* __restrict__ out)
{
    int idx = blockIdx.x * 256 + threadIdx.x;
    if (idx < (BB * SS * DD) / 4) {
        float4 a = *(const float4*)&g_part[0][idx * 4];
        float4 b = *(const float4*)&g_part[1][idx * 4];
        float4 c = *(const float4*)&g_part[2][idx * 4];
        float4 d = *(const float4*)&g_part[3][idx * 4];
        *(float4*)&out[idx * 4] = make_float4(a.x + b.x + c.x + d.x, a.y + b.y + c.y + d.y,
                                              a.z + b.z + c.z + d.z, a.w + b.w + c.w + d.w);
    }
}

// ---------------------------------------------------------------------------
// Inputs: x, mask0, wq, wk, wv, wo, q_norm_w, k_norm_w
// ---------------------------------------------------------------------------
extern "C" void kernel_launch(void* const* d_in, const int* in_sizes, int n_in,
                              void* d_out, int out_size)
{
    const float* x     = (const float*)d_in[0];
    const float* mask0 = (const float*)d_in[1];
    const float* wq    = (const float*)d_in[2];
    const float* wk    = (const float*)d_in[3];
    const float* wv    = (const float*)d_in[4];
    const float* wo    = (const float*)d_in[5];
    const float* qnw   = (const float*)d_in[6];
    const float* knw   = (const float*)d_in[7];
    float* out = (float*)d_out;

    cudaFuncSetAttribute(attn_kernel, cudaFuncAttributeMaxDynamicSharedMemorySize, AT_SMEM);

    qkv_kernel<<<dim3(64, 32, 3), 256>>>(x, wq, wk, wv);
    normrope_kernel<<<BB * SS * HH, 128>>>(qnw, knw);
    attn_kernel<<<dim3(SS / 128, HH, BB), 256, AT_SMEM>>>(mask0);
    oproj_part_kernel<<<dim3(64, 3, 4), 256>>>(wo);
    oproj_reduce_kernel<<<768, 256>>>(out);
}

// round 7
// speedup vs baseline: 4.5972x; 1.9108x over previous
// R7: fp16 mma.sync everywhere (qkv, attn, oproj); RoPE table init; K fp16-resident.
#include <cuda_runtime.h>
#include <cuda_fp16.h>
#include <math.h>
#include <stdint.h>
#include <stddef.h>

#define BB 2
#define SS 2048
#define DD 192
#define HH 16
#define HDIM 128

typedef unsigned long long u64;
typedef unsigned int u32;

// ---- fp16 helpers ----
__device__ __forceinline__ u32 h2(float a, float b) {
    __half2 h = __floats2half2_rn(a, b);
    return *(u32*)&h;
}
__device__ __forceinline__ void mma_f16(float d[4], u32 a0, u32 a1, u32 a2, u32 a3,
                                        u32 b0, u32 b1) {
    asm volatile(
        "mma.sync.aligned.m16n8k16.row.col.f32.f16.f16.f32 "
        "{%0,%1,%2,%3}, {%4,%5,%6,%7}, {%8,%9}, {%0,%1,%2,%3};\n"
        : "+f"(d[0]), "+f"(d[1]), "+f"(d[2]), "+f"(d[3])
        : "r"(a0), "r"(a1), "r"(a2), "r"(a3), "r"(b0), "r"(b1));
}

// Scratch
__device__ float g_q[BB * HH * SS * HDIM];
__device__ float g_k[BB * HH * SS * HDIM];
__device__ float g_v[BB * HH * SS * HDIM];
__device__ __half g_kh[BB * HH * SS * HDIM];
__device__ float g_attn[BB * SS * HH * HDIM];
__device__ float g_part[4][BB * SS * DD];
__device__ float g_cos[SS * 64];
__device__ float g_sin[SS * 64];

// ---------------------------------------------------------------------------
// Kernel 0: RoPE cos/sin table (once per launch; deterministic).
// ---------------------------------------------------------------------------
__global__ __launch_bounds__(256) void rope_init_kernel()
{
    int i = blockIdx.x * 256 + threadIdx.x;   // [0, 2048*64)
    int s = i >> 6, p = i & 63;
    double inv = exp((double)p * -0.21586735246819178);  // -ln(1e6)/64
    double ang = fmod((double)s * inv, 6.283185307179586476925287);
    float a = (float)ang;
    g_cos[i] = cosf(a);
    g_sin[i] = sinf(a);
}

// ---------------------------------------------------------------------------
// Kernel 1: QKV projection, fp16 mma. grid (32, 32, 3), block 256 (8 warps).
// C[m][n] = sum_k x[m][k] w[n][k].  M-tile 128, N-tile 64, K=192 staged once.
// smem u32 pair arrays stride 100 (bank = 4g+q4: conflict-free fragments).
// ---------------------------------------------------------------------------
#define QKV_SMEM ((128 * 100 + 64 * 100) * 4)

__global__ __launch_bounds__(256) void qkv_kernel(
    const float* __restrict__ x, const float* __restrict__ wq,
    const float* __restrict__ wk, const float* __restrict__ wv)
{
    extern __shared__ u32 qsm[];
    u32* sX = qsm;              // [128][100]
    u32* sW = qsm + 128 * 100;  // [64][100]
    const int tid = threadIdx.x;
    const int wid = tid >> 5, lane = tid & 31;
    const int g = lane >> 2, q4 = lane & 3;
    const int rw = wid & 3, cw = wid >> 2;
    const int m0 = blockIdx.x * 128;
    const int n0 = blockIdx.y * 64;
    const int z = blockIdx.z;
    const float* w = (z == 0) ? wq : (z == 1) ? wk : wv;
    float* dst = (z == 0) ? g_q : (z == 1) ? g_k : g_v;

    #pragma unroll
    for (int it = 0; it < 24; it++) {
        int idx = tid + it * 256;
        int r = idx / 48, l = idx % 48;
        float4 v = *(const float4*)&x[(size_t)(m0 + r) * 192 + 4 * l];
        sX[r * 100 + 2 * l] = h2(v.x, v.y);
        sX[r * 100 + 2 * l + 1] = h2(v.z, v.w);
    }
    #pragma unroll
    for (int it = 0; it < 12; it++) {
        int idx = tid + it * 256;
        int r = idx / 48, l = idx % 48;
        float4 v = *(const float4*)&w[(size_t)(n0 + r) * 192 + 4 * l];
        sW[r * 100 + 2 * l] = h2(v.x, v.y);
        sW[r * 100 + 2 * l + 1] = h2(v.z, v.w);
    }
    __syncthreads();

    float acc[2][4][4];
    #pragma unroll
    for (int mt = 0; mt < 2; mt++)
        #pragma unroll
        for (int nt = 0; nt < 4; nt++)
            #pragma unroll
            for (int c = 0; c < 4; c++) acc[mt][nt][c] = 0.0f;

    #pragma unroll
    for (int kk = 0; kk < 12; kk++) {
        u32 a[2][4];
        #pragma unroll
        for (int mt = 0; mt < 2; mt++) {
            int base = (32 * rw + 16 * mt + g) * 100 + 8 * kk + q4;
            a[mt][0] = sX[base];
            a[mt][1] = sX[base + 800];
            a[mt][2] = sX[base + 4];
            a[mt][3] = sX[base + 804];
        }
        #pragma unroll
        for (int nt = 0; nt < 4; nt++) {
            int nb = (32 * cw + 8 * nt + g) * 100 + 8 * kk + q4;
            u32 b0 = sW[nb], b1 = sW[nb + 4];
            mma_f16(acc[0][nt], a[0][0], a[0][1], a[0][2], a[0][3], b0, b1);
            mma_f16(acc[1][nt], a[1][0], a[1][1], a[1][2], a[1][3], b0, b1);
        }
    }

    #pragma unroll
    for (int mt = 0; mt < 2; mt++) {
        int mrow = m0 + 32 * rw + 16 * mt + g;
        int b_ = mrow >> 11, s_ = mrow & 2047;
        #pragma unroll
        for (int nt = 0; nt < 4; nt++) {
            int n = n0 + 32 * cw + 8 * nt + 2 * q4;
            int h_ = n >> 7, hd = n & 127;
            size_t o = ((size_t)(b_ * HH + h_) * SS + s_) * HDIM + hd;
            *(float2*)&dst[o] = make_float2(acc[mt][nt][0], acc[mt][nt][1]);
            *(float2*)&dst[o + 8 * HDIM] = make_float2(acc[mt][nt][2], acc[mt][nt][3]);
        }
    }
}

// ---------------------------------------------------------------------------
// Kernel 2: per-head RMSNorm + RoPE (table lookup). q -> fp32, k -> fp16.
// ---------------------------------------------------------------------------
__global__ __launch_bounds__(128) void normrope_kernel(
    const float* __restrict__ qw, const float* __restrict__ kw)
{
    __shared__ float sq[128], sk[128], red[8];
    const int bs = blockIdx.x;
    const int h = bs & 15;
    const int s = (bs >> 4) & 2047;
    const int b = bs >> 15;
    const int hd = threadIdx.x;
    const size_t base = ((size_t)(b * HH + h) * SS + s) * HDIM + hd;

    float qv = g_q[base];
    float kv = g_k[base];
    float q2 = qv * qv, k2 = kv * kv;
    #pragma unroll
    for (int off = 16; off; off >>= 1) {
        q2 += __shfl_xor_sync(0xffffffffu, q2, off);
        k2 += __shfl_xor_sync(0xffffffffu, k2, off);
    }
    if ((hd & 31) == 0) { red[hd >> 5] = q2; red[4 + (hd >> 5)] = k2; }
    __syncthreads();
    float qs = red[0] + red[1] + red[2] + red[3];
    float ks = red[4] + red[5] + red[6] + red[7];
    float qr = rsqrtf(qs * (1.0f / 128.0f) + 1e-6f);
    float kr = rsqrtf(ks * (1.0f / 128.0f) + 1e-6f);
    float qn = qv * qr * qw[hd];
    float kn = kv * kr * kw[hd];
    sq[hd] = qn; sk[hd] = kn;
    __syncthreads();

    int p = hd & 63;
    float cs = g_cos[s * 64 + p];
    float sn = g_sin[s * 64 + p];
    float qrot = (hd < 64) ? -sq[hd + 64] : sq[hd - 64];
    float krot = (hd < 64) ? -sk[hd + 64] : sk[hd - 64];
    g_q[base] = qn * cs + qrot * sn;
    g_kh[base] = __float2half(kn * cs + krot * sn);
}

// ---------------------------------------------------------------------------
// Kernel 3: flash attention, fp16 mma. grid (16, 16, 2), block 256 (8 warps).
// Same as R6 except K tiles come pre-converted (g_kh) as raw uint4 copies.
// ---------------------------------------------------------------------------
#define SKB 0
#define SVB 17408
#define SPB 35840
#define SLB 54272
#define AT_SMEM (SLB + 1024)

#define QSCALE (0.08838834764831845f * 1.4426950408889634f)
#define LOG2E 1.4426950408889634f
#define EOFF (4.0f * 1.4426950408889634f)

__global__ __launch_bounds__(256, 1) void attn_kernel(const float* __restrict__ mask)
{
    extern __shared__ __align__(16) char smc[];
    u32* sK = (u32*)(smc + SKB);       // [64][68] key x d-pairs (fp16)
    u32* sV = (u32*)(smc + SVB);       // [128][36] d x key-pairs
    u32* sP = (u32*)(smc + SPB);       // [128][36] row x key-pairs
    float* sL = (float*)(smc + SLB);

    const int tid = threadIdx.x;
    const int wid = tid >> 5, lane = tid & 31;
    const int g = lane >> 2, q4 = lane & 3;
    const int rw = wid & 3, cw = wid >> 2;

    const int q0 = blockIdx.x * 128;
    const int h = blockIdx.y, b = blockIdx.z;
    const size_t bh = (size_t)(b * HH + h) * SS * HDIM;
    const float* Qg = g_q + bh;
    const __half* Kg = g_kh + bh;
    const float* Vg = g_v + bh;
    const float* mbase = mask + (size_t)b * SS * SS;

    // Q fragments -> registers (scaled, fp16)
    u32 qf[2][8][4];
    #pragma unroll
    for (int mt = 0; mt < 2; mt++)
        #pragma unroll
        for (int kk = 0; kk < 8; kk++) {
            const float* qp = &Qg[(size_t)(q0 + 32 * rw + 16 * mt + g) * HDIM + 2 * q4 + 16 * kk];
            float2 v0 = *(const float2*)qp;
            float2 v1 = *(const float2*)(qp + 8 * HDIM);
            float2 v2 = *(const float2*)(qp + 8);
            float2 v3 = *(const float2*)(qp + 8 * HDIM + 8);
            qf[mt][kk][0] = h2(v0.x * QSCALE, v0.y * QSCALE);
            qf[mt][kk][1] = h2(v1.x * QSCALE, v1.y * QSCALE);
            qf[mt][kk][2] = h2(v2.x * QSCALE, v2.y * QSCALE);
            qf[mt][kk][3] = h2(v3.x * QSCALE, v3.y * QSCALE);
        }

    float o[2][8][4];
    #pragma unroll
    for (int mt = 0; mt < 2; mt++)
        #pragma unroll
        for (int nt = 0; nt < 8; nt++)
            #pragma unroll
            for (int c = 0; c < 4; c++) o[mt][nt][c] = 0.0f;
    float rsum[2][2] = {};

    for (int kt = 0; kt < 32; kt++) {
        const int k0 = kt * 64;
        __syncthreads();

        // K: raw fp16 copy, [key][d-pairs]
        #pragma unroll
        for (int it = 0; it < 4; it++) {
            int idx = tid + it * 256;
            int t = idx >> 4, l = idx & 15;
            uint4 v = *(const uint4*)&Kg[(size_t)(k0 + t) * HDIM + 8 * l];
            *(uint4*)&sK[t * 68 + 4 * l] = v;
        }
        // V transposed: [d][key-pairs]
        #pragma unroll
        for (int it = 0; it < 4; it++) {
            int idx = tid + it * 256;
            int l = idx & 31, t = idx >> 5;
            const float* va = &Vg[(size_t)(k0 + 2 * t) * HDIM + 4 * l];
            float4 A4 = *(const float4*)va;
            float4 B4 = *(const float4*)(va + HDIM);
            sV[(4 * l + 0) * 36 + t] = h2(A4.x, B4.x);
            sV[(4 * l + 1) * 36 + t] = h2(A4.y, B4.y);
            sV[(4 * l + 2) * 36 + t] = h2(A4.z, B4.z);
            sV[(4 * l + 3) * 36 + t] = h2(A4.w, B4.w);
        }
        __syncthreads();

        // QK^T (A = registers, B = sK)
        float acc[2][4][4];
        #pragma unroll
        for (int mt = 0; mt < 2; mt++)
            #pragma unroll
            for (int nt = 0; nt < 4; nt++)
                #pragma unroll
                for (int c = 0; c < 4; c++) acc[mt][nt][c] = 0.0f;
        #pragma unroll
        for (int kk = 0; kk < 8; kk++) {
            #pragma unroll
            for (int nt = 0; nt < 4; nt++) {
                int key = 32 * cw + 8 * nt + g;
                u32 b0 = sK[key * 68 + 8 * kk + q4];
                u32 b1 = sK[key * 68 + 8 * kk + q4 + 4];
                mma_f16(acc[0][nt], qf[0][kk][0], qf[0][kk][1], qf[0][kk][2], qf[0][kk][3], b0, b1);
                mma_f16(acc[1][nt], qf[1][kk][0], qf[1][kk][1], qf[1][kk][2], qf[1][kk][3], b0, b1);
            }
        }

        // softmax epilogue (max-free, exp2 domain)
        #pragma unroll
        for (int mt = 0; mt < 2; mt++) {
            int row0 = 32 * rw + 16 * mt + g;
            #pragma unroll
            for (int nt = 0; nt < 4; nt++) {
                const float* mp = &mbase[(size_t)(q0 + row0) * SS + k0 + 32 * cw + 8 * nt + 2 * q4];
                float2 m0 = *(const float2*)mp;
                float2 m1 = *(const float2*)(mp + 8 * SS);
                float e0 = exp2f(acc[mt][nt][0] + m0.x * LOG2E - EOFF);
                float e1 = exp2f(acc[mt][nt][1] + m0.y * LOG2E - EOFF);
                float e2 = exp2f(acc[mt][nt][2] + m1.x * LOG2E - EOFF);
                float e3 = exp2f(acc[mt][nt][3] + m1.y * LOG2E - EOFF);
                rsum[mt][0] += e0 + e1;
                rsum[mt][1] += e2 + e3;
                sP[row0 * 36 + 16 * cw + 4 * nt + q4] = h2(e0, e1);
                sP[(row0 + 8) * 36 + 16 * cw + 4 * nt + q4] = h2(e2, e3);
            }
        }
        __syncthreads();

        // PV (A = sP, B = sV)
        #pragma unroll
        for (int kk = 0; kk < 4; kk++) {
            u32 a[2][4];
            #pragma unroll
            for (int mt = 0; mt < 2; mt++) {
                int row0 = 32 * rw + 16 * mt + g;
                a[mt][0] = sP[row0 * 36 + q4 + 8 * kk];
                a[mt][1] = sP[(row0 + 8) * 36 + q4 + 8 * kk];
                a[mt][2] = sP[row0 * 36 + q4 + 4 + 8 * kk];
                a[mt][3] = sP[(row0 + 8) * 36 + q4 + 4 + 8 * kk];
            }
            #pragma unroll
            for (int nt = 0; nt < 8; nt++) {
                int d = 64 * cw + 8 * nt + g;
                u32 b0 = sV[d * 36 + q4 + 8 * kk];
                u32 b1 = sV[d * 36 + q4 + 4 + 8 * kk];
                mma_f16(o[0][nt], a[0][0], a[0][1], a[0][2], a[0][3], b0, b1);
                mma_f16(o[1][nt], a[1][0], a[1][1], a[1][2], a[1][3], b0, b1);
            }
        }
    }

    // finalize
    #pragma unroll
    for (int mt = 0; mt < 2; mt++)
        #pragma unroll
        for (int half = 0; half < 2; half++) {
            float s = rsum[mt][half];
            s += __shfl_xor_sync(0xffffffffu, s, 1);
            s += __shfl_xor_sync(0xffffffffu, s, 2);
            rsum[mt][half] = s;
        }
    if (q4 == 0) {
        #pragma unroll
        for (int mt = 0; mt < 2; mt++) {
            sL[cw * 128 + 32 * rw + 16 * mt + g] = rsum[mt][0];
            sL[cw * 128 + 32 * rw + 16 * mt + g + 8] = rsum[mt][1];
        }
    }
    __syncthreads();

    #pragma unroll
    for (int mt = 0; mt < 2; mt++) {
        int row0 = 32 * rw + 16 * mt + g;
        float inv0 = 1.0f / (sL[row0] + sL[128 + row0]);
        float inv1 = 1.0f / (sL[row0 + 8] + sL[128 + row0 + 8]);
        #pragma unroll
        for (int nt = 0; nt < 8; nt++) {
            int d = 64 * cw + 8 * nt + 2 * q4;
            size_t ob0 = (size_t)(b * SS + q0 + row0) * (HH * HDIM) + h * HDIM + d;
            size_t ob1 = (size_t)(b * SS + q0 + row0 + 8) * (HH * HDIM) + h * HDIM + d;
            *(float2*)&g_attn[ob0] = make_float2(o[mt][nt][0] * inv0, o[mt][nt][1] * inv0);
            *(float2*)&g_attn[ob1] = make_float2(o[mt][nt][2] * inv1, o[mt][nt][3] * inv1);
        }
    }
}

// ---------------------------------------------------------------------------
// Kernel 4a: output projection, fp16 mma, split-K=4. grid (32, 3, 4), block 256.
// out_part[m][n] = sum_{k in chunk} attn[m][k] wo[n][k].  K-chunks of 64.
// ---------------------------------------------------------------------------
__global__ __launch_bounds__(256) void oproj_part_kernel(const float* __restrict__ wo)
{
    __shared__ u32 sA[128 * 36];
    __shared__ u32 sB[64 * 36];
    const int tid = threadIdx.x;
    const int wid = tid >> 5, lane = tid & 31;
    const int g = lane >> 2, q4 = lane & 3;
    const int rw = wid & 3, cw = wid >> 2;
    const int m0 = blockIdx.x * 128;
    const int n0 = blockIdx.y * 64;
    const int kt = blockIdx.z;

    float acc[2][4][4];
    #pragma unroll
    for (int mt = 0; mt < 2; mt++)
        #pragma unroll
        for (int nt = 0; nt < 4; nt++)
            #pragma unroll
            for (int c = 0; c < 4; c++) acc[mt][nt][c] = 0.0f;

    for (int kb = kt * 512; kb < kt * 512 + 512; kb += 64) {
        __syncthreads();
        #pragma unroll
        for (int it = 0; it < 8; it++) {
            int idx = tid + it * 256;
            int r = idx >> 4, l = idx & 15;
            float4 v = *(const float4*)&g_attn[(size_t)(m0 + r) * 2048 + kb + 4 * l];
            sA[r * 36 + 2 * l] = h2(v.x, v.y);
            sA[r * 36 + 2 * l + 1] = h2(v.z, v.w);
        }
        #pragma unroll
        for (int it = 0; it < 4; it++) {
            int idx = tid + it * 256;
            int r = idx >> 4, l = idx & 15;
            float4 v = *(const float4*)&wo[(size_t)(n0 + r) * 2048 + kb + 4 * l];
            sB[r * 36 + 2 * l] = h2(v.x, v.y);
            sB[r * 36 + 2 * l + 1] = h2(v.z, v.w);
        }
        __syncthreads();
        #pragma unroll
        for (int kk = 0; kk < 4; kk++) {
            u32 a[2][4];
            #pragma unroll
            for (int mt = 0; mt < 2; mt++) {
                int base = (32 * rw + 16 * mt + g) * 36 + 8 * kk + q4;
                a[mt][0] = sA[base];
                a[mt][1] = sA[base + 288];
                a[mt][2] = sA[base + 4];
                a[mt][3] = sA[base + 292];
            }
            #pragma unroll
            for (int nt = 0; nt < 4; nt++) {
                int nb = (32 * cw + 8 * nt + g) * 36 + 8 * kk + q4;
                u32 b0 = sB[nb], b1 = sB[nb + 4];
                mma_f16(acc[0][nt], a[0][0], a[0][1], a[0][2], a[0][3], b0, b1);
                mma_f16(acc[1][nt], a[1][0], a[1][1], a[1][2], a[1][3], b0, b1);
            }
        }
    }

    #pragma unroll
    for (int mt = 0; mt < 2; mt++) {
        int mrow = m0 + 32 * rw + 16 * mt + g;
        #pragma unroll
        for (int nt = 0; nt < 4; nt++) {
            int n = n0 + 32 * cw + 8 * nt + 2 * q4;
            float* pp = &g_part[kt][(size_t)mrow * DD + n];
            *(float2*)pp = make_float2(acc[mt][nt][0], acc[mt][nt][1]);
            *(float2*)(pp + 8 * DD) = make_float2(acc[mt][nt][2], acc[mt][nt][3]);
        }
    }
}

__global__ __launch_bounds__(256) void oproj_reduce_kernel(float* __restrict__ out)
{
    int idx = blockIdx.x * 256 + threadIdx.x;
    if (idx < (BB * SS * DD) / 4) {
        float4 a = *(const float4*)&g_part[0][idx * 4];
        float4 b = *(const float4*)&g_part[1][idx * 4];
        float4 c = *(const float4*)&g_part[2][idx * 4];
        float4 d = *(const float4*)&g_part[3][idx * 4];
        *(float4*)&out[idx * 4] = make_float4(a.x + b.x + c.x + d.x, a.y + b.y + c.y + d.y,
                                              a.z + b.z + c.z + d.z, a.w + b.w + c.w + d.w);
    }
}

// ---------------------------------------------------------------------------
// Inputs: x, mask0, wq, wk, wv, wo, q_norm_w, k_norm_w
// ---------------------------------------------------------------------------
extern "C" void kernel_launch(void* const* d_in, const int* in_sizes, int n_in,
                              void* d_out, int out_size)
{
    const float* x     = (const float*)d_in[0];
    const float* mask0 = (const float*)d_in[1];
    const float* wq    = (const float*)d_in[2];
    const float* wk    = (const float*)d_in[3];
    const float* wv    = (const float*)d_in[4];
    const float* wo    = (const float*)d_in[5];
    const float* qnw   = (const float*)d_in[6];
    const float* knw   = (const float*)d_in[7];
    float* out = (float*)d_out;

    cudaFuncSetAttribute(qkv_kernel, cudaFuncAttributeMaxDynamicSharedMemorySize, QKV_SMEM);
    cudaFuncSetAttribute(attn_kernel, cudaFuncAttributeMaxDynamicSharedMemorySize, AT_SMEM);

    rope_init_kernel<<<SS * 64 / 256, 256>>>();
    qkv_kernel<<<dim3(32, 32, 3), 256, QKV_SMEM>>>(x, wq, wk, wv);
    normrope_kernel<<<BB * SS * HH, 128>>>(qnw, knw);
    attn_kernel<<<dim3(SS / 128, HH, BB), 256, AT_SMEM>>>(mask0);
    oproj_part_kernel<<<dim3(32, 3, 4), 256>>>(wo);
    oproj_reduce_kernel<<<768, 256>>>(out);
}

// round 8
// speedup vs baseline: 5.7949x; 1.2605x over previous
// R8: cp.async double-buffered K/V in attention; V pre-transposed to fp16.
#include <cuda_runtime.h>
#include <cuda_fp16.h>
#include <math.h>
#include <stdint.h>
#include <stddef.h>

#define BB 2
#define SS 2048
#define DD 192
#define HH 16
#define HDIM 128

typedef unsigned long long u64;
typedef unsigned int u32;

// ---- fp16 helpers ----
__device__ __forceinline__ u32 h2(float a, float b) {
    __half2 h = __floats2half2_rn(a, b);
    return *(u32*)&h;
}
__device__ __forceinline__ void mma_f16(float d[4], u32 a0, u32 a1, u32 a2, u32 a3,
                                        u32 b0, u32 b1) {
    asm volatile(
        "mma.sync.aligned.m16n8k16.row.col.f32.f16.f16.f32 "
        "{%0,%1,%2,%3}, {%4,%5,%6,%7}, {%8,%9}, {%0,%1,%2,%3};\n"
        : "+f"(d[0]), "+f"(d[1]), "+f"(d[2]), "+f"(d[3])
        : "r"(a0), "r"(a1), "r"(a2), "r"(a3), "r"(b0), "r"(b1));
}
__device__ __forceinline__ u32 smem_u32(const void* p) {
    u32 a; asm("{.reg .u64 t; cvta.to.shared.u64 t, %1; cvt.u32.u64 %0, t;}" : "=r"(a) : "l"(p));
    return a;
}
__device__ __forceinline__ void cpa16(u32 dst, const void* src) {
    asm volatile("cp.async.cg.shared.global [%0], [%1], 16;" :: "r"(dst), "l"(src));
}
#define CPA_COMMIT() asm volatile("cp.async.commit_group;" ::: "memory")
#define CPA_WAIT1()  asm volatile("cp.async.wait_group 1;" ::: "memory")

// Scratch
__device__ float g_q[BB * HH * SS * HDIM];
__device__ float g_k[BB * HH * SS * HDIM];
__device__ float g_v[BB * HH * SS * HDIM];
__device__ __half g_kh[BB * HH * SS * HDIM];
__device__ __half g_vh[BB * HH * HDIM * SS];   // transposed: [b][h][d][s]
__device__ float g_attn[BB * SS * HH * HDIM];
__device__ float g_part[4][BB * SS * DD];
__device__ float g_cos[SS * 64];
__device__ float g_sin[SS * 64];

// ---------------------------------------------------------------------------
// Kernel 0: RoPE cos/sin table.
// ---------------------------------------------------------------------------
__global__ __launch_bounds__(256) void rope_init_kernel()
{
    int i = blockIdx.x * 256 + threadIdx.x;
    int s = i >> 6, p = i & 63;
    double inv = exp((double)p * -0.21586735246819178);
    double ang = fmod((double)s * inv, 6.283185307179586476925287);
    float a = (float)ang;
    g_cos[i] = cosf(a);
    g_sin[i] = sinf(a);
}

// ---------------------------------------------------------------------------
// Kernel 1: QKV projection, fp16 mma. grid (32, 32, 3), block 256.
// ---------------------------------------------------------------------------
#define QKV_SMEM ((128 * 100 + 64 * 100) * 4)

__global__ __launch_bounds__(256) void qkv_kernel(
    const float* __restrict__ x, const float* __restrict__ wq,
    const float* __restrict__ wk, const float* __restrict__ wv)
{
    extern __shared__ u32 qsm[];
    u32* sX = qsm;
    u32* sW = qsm + 128 * 100;
    const int tid = threadIdx.x;
    const int wid = tid >> 5, lane = tid & 31;
    const int g = lane >> 2, q4 = lane & 3;
    const int rw = wid & 3, cw = wid >> 2;
    const int m0 = blockIdx.x * 128;
    const int n0 = blockIdx.y * 64;
    const int z = blockIdx.z;
    const float* w = (z == 0) ? wq : (z == 1) ? wk : wv;
    float* dst = (z == 0) ? g_q : (z == 1) ? g_k : g_v;

    #pragma unroll
    for (int it = 0; it < 24; it++) {
        int idx = tid + it * 256;
        int r = idx / 48, l = idx % 48;
        float4 v = *(const float4*)&x[(size_t)(m0 + r) * 192 + 4 * l];
        sX[r * 100 + 2 * l] = h2(v.x, v.y);
        sX[r * 100 + 2 * l + 1] = h2(v.z, v.w);
    }
    #pragma unroll
    for (int it = 0; it < 12; it++) {
        int idx = tid + it * 256;
        int r = idx / 48, l = idx % 48;
        float4 v = *(const float4*)&w[(size_t)(n0 + r) * 192 + 4 * l];
        sW[r * 100 + 2 * l] = h2(v.x, v.y);
        sW[r * 100 + 2 * l + 1] = h2(v.z, v.w);
    }
    __syncthreads();

    float acc[2][4][4];
    #pragma unroll
    for (int mt = 0; mt < 2; mt++)
        #pragma unroll
        for (int nt = 0; nt < 4; nt++)
            #pragma unroll
            for (int c = 0; c < 4; c++) acc[mt][nt][c] = 0.0f;

    #pragma unroll
    for (int kk = 0; kk < 12; kk++) {
        u32 a[2][4];
        #pragma unroll
        for (int mt = 0; mt < 2; mt++) {
            int base = (32 * rw + 16 * mt + g) * 100 + 8 * kk + q4;
            a[mt][0] = sX[base];
            a[mt][1] = sX[base + 800];
            a[mt][2] = sX[base + 4];
            a[mt][3] = sX[base + 804];
        }
        #pragma unroll
        for (int nt = 0; nt < 4; nt++) {
            int nb = (32 * cw + 8 * nt + g) * 100 + 8 * kk + q4;
            u32 b0 = sW[nb], b1 = sW[nb + 4];
            mma_f16(acc[0][nt], a[0][0], a[0][1], a[0][2], a[0][3], b0, b1);
            mma_f16(acc[1][nt], a[1][0], a[1][1], a[1][2], a[1][3], b0, b1);
        }
    }

    #pragma unroll
    for (int mt = 0; mt < 2; mt++) {
        int mrow = m0 + 32 * rw + 16 * mt + g;
        int b_ = mrow >> 11, s_ = mrow & 2047;
        #pragma unroll
        for (int nt = 0; nt < 4; nt++) {
            int n = n0 + 32 * cw + 8 * nt + 2 * q4;
            int h_ = n >> 7, hd = n & 127;
            size_t o = ((size_t)(b_ * HH + h_) * SS + s_) * HDIM + hd;
            *(float2*)&dst[o] = make_float2(acc[mt][nt][0], acc[mt][nt][1]);
            *(float2*)&dst[o + 8 * HDIM] = make_float2(acc[mt][nt][2], acc[mt][nt][3]);
        }
    }
}

// ---------------------------------------------------------------------------
// Kernel 1b: V transpose+convert  g_v[b][h][s][d] f32 -> g_vh[b][h][d][s] f16.
// grid (SS/64, HDIM/64, BB*HH), block 256.  64x64 tiles via padded smem.
// ---------------------------------------------------------------------------
__global__ __launch_bounds__(256) void vtrans_kernel()
{
    __shared__ float ts[64 * 65];
    const int tid = threadIdx.x;
    const int s0 = blockIdx.x * 64, d0 = blockIdx.y * 64;
    const size_t bh = (size_t)blockIdx.z;
    const float* src = g_v + bh * SS * HDIM;
    __half* dst = g_vh + bh * HDIM * SS;

    #pragma unroll
    for (int it = 0; it < 4; it++) {
        int idx = tid + it * 256;               // 1024 float4 = 64x64
        int r = idx >> 4, c = (idx & 15) * 4;   // r = s-row, c = d
        float4 v = *(const float4*)&src[(size_t)(s0 + r) * HDIM + d0 + c];
        ts[(c + 0) * 65 + r] = v.x;
        ts[(c + 1) * 65 + r] = v.y;
        ts[(c + 2) * 65 + r] = v.z;
        ts[(c + 3) * 65 + r] = v.w;
    }
    __syncthreads();
    #pragma unroll
    for (int it = 0; it < 8; it++) {
        int idx = tid + it * 256;               // 2048 half2 = 64x64
        int r = idx >> 5, c = (idx & 31) * 2;   // r = d-row, c = s
        __half2 h = __floats2half2_rn(ts[r * 65 + c], ts[r * 65 + c + 1]);
        *(__half2*)&dst[(size_t)(d0 + r) * SS + s0 + c] = h;
    }
}

// ---------------------------------------------------------------------------
// Kernel 2: per-head RMSNorm + RoPE (table lookup). q -> fp32, k -> fp16.
// ---------------------------------------------------------------------------
__global__ __launch_bounds__(128) void normrope_kernel(
    const float* __restrict__ qw, const float* __restrict__ kw)
{
    __shared__ float sq[128], sk[128], red[8];
    const int bs = blockIdx.x;
    const int h = bs & 15;
    const int s = (bs >> 4) & 2047;
    const int b = bs >> 15;
    const int hd = threadIdx.x;
    const size_t base = ((size_t)(b * HH + h) * SS + s) * HDIM + hd;

    float qv = g_q[base];
    float kv = g_k[base];
    float q2 = qv * qv, k2 = kv * kv;
    #pragma unroll
    for (int off = 16; off; off >>= 1) {
        q2 += __shfl_xor_sync(0xffffffffu, q2, off);
        k2 += __shfl_xor_sync(0xffffffffu, k2, off);
    }
    if ((hd & 31) == 0) { red[hd >> 5] = q2; red[4 + (hd >> 5)] = k2; }
    __syncthreads();
    float qs = red[0] + red[1] + red[2] + red[3];
    float ks = red[4] + red[5] + red[6] + red[7];
    float qr = rsqrtf(qs * (1.0f / 128.0f) + 1e-6f);
    float kr = rsqrtf(ks * (1.0f / 128.0f) + 1e-6f);
    float qn = qv * qr * qw[hd];
    float kn = kv * kr * kw[hd];
    sq[hd] = qn; sk[hd] = kn;
    __syncthreads();

    int p = hd & 63;
    float cs = g_cos[s * 64 + p];
    float sn = g_sin[s * 64 + p];
    float qrot = (hd < 64) ? -sq[hd + 64] : sq[hd - 64];
    float krot = (hd < 64) ? -sk[hd + 64] : sk[hd - 64];
    g_q[base] = qn * cs + qrot * sn;
    g_kh[base] = __float2half(kn * cs + krot * sn);
}

// ---------------------------------------------------------------------------
// Kernel 3: flash attention, fp16 mma + cp.async double-buffered K/V.
// grid (16, 16, 2), block 256 (8 warps).  2 syncthreads per tile.
// ---------------------------------------------------------------------------
#define SKB 0
#define SK_BYTES 17408                 // 64 * 68 * 4 per buffer
#define SVB (2 * SK_BYTES)             // 34816
#define SV_BYTES 18432                 // 128 * 36 * 4 per buffer
#define SPB (SVB + 2 * SV_BYTES)       // 71680
#define SLB (SPB + 18432)              // 90112
#define AT_SMEM (SLB + 1024)           // 91136

#define QSCALE (0.08838834764831845f * 1.4426950408889634f)
#define LOG2E 1.4426950408889634f
#define EOFF (4.0f * 1.4426950408889634f)

__global__ __launch_bounds__(256, 1) void attn_kernel(const float* __restrict__ mask)
{
    extern __shared__ __align__(16) char smc[];
    u32* sP = (u32*)(smc + SPB);
    float* sL = (float*)(smc + SLB);
    const u32 sbase = smem_u32(smc);

    const int tid = threadIdx.x;
    const int wid = tid >> 5, lane = tid & 31;
    const int g = lane >> 2, q4 = lane & 3;
    const int rw = wid & 3, cw = wid >> 2;

    const int q0 = blockIdx.x * 128;
    const int h = blockIdx.y, b = blockIdx.z;
    const size_t bh = (size_t)(b * HH + h) * SS * HDIM;
    const float* Qg = g_q + bh;
    const __half* Kg = g_kh + bh;
    const __half* Vg = g_vh + bh;       // [d][s]
    const float* mbase = mask + (size_t)b * SS * SS;

    // per-thread cp.async slices (4 chunks K, 4 chunks V)
    const int krow = tid >> 2, kchunk = tid & 3;        // K: rows 0..63, 4 thr/row x 4 it
    const int vrow = tid >> 1, vchunk = tid & 1;        // V: rows 0..127, 2 thr/row x 4 it

    // Q fragments -> registers
    u32 qf[2][8][4];
    #pragma unroll
    for (int mt = 0; mt < 2; mt++)
        #pragma unroll
        for (int kk = 0; kk < 8; kk++) {
            const float* qp = &Qg[(size_t)(q0 + 32 * rw + 16 * mt + g) * HDIM + 2 * q4 + 16 * kk];
            float2 v0 = *(const float2*)qp;
            float2 v1 = *(const float2*)(qp + 8 * HDIM);
            float2 v2 = *(const float2*)(qp + 8);
            float2 v3 = *(const float2*)(qp + 8 * HDIM + 8);
            qf[mt][kk][0] = h2(v0.x * QSCALE, v0.y * QSCALE);
            qf[mt][kk][1] = h2(v1.x * QSCALE, v1.y * QSCALE);
            qf[mt][kk][2] = h2(v2.x * QSCALE, v2.y * QSCALE);
            qf[mt][kk][3] = h2(v3.x * QSCALE, v3.y * QSCALE);
        }

    float o[2][8][4];
    #pragma unroll
    for (int mt = 0; mt < 2; mt++)
        #pragma unroll
        for (int nt = 0; nt < 8; nt++)
            #pragma unroll
            for (int c = 0; c < 4; c++) o[mt][nt][c] = 0.0f;
    float rsum[2][2] = {};

    // prefetch tile 0 into buffer 0
    {
        const int k0 = 0;
        u32 kdst = sbase + SKB + krow * 272 + kchunk * 16;
        u32 vdst = sbase + SVB + vrow * 144 + vchunk * 16;
        #pragma unroll
        for (int it = 0; it < 4; it++)
            cpa16(kdst + it * 64, &Kg[(size_t)(k0 + krow) * HDIM + (kchunk + 4 * it) * 8]);
        #pragma unroll
        for (int it = 0; it < 4; it++)
            cpa16(vdst + it * 32, &Vg[(size_t)vrow * SS + k0 + (vchunk + 2 * it) * 8]);
    }
    CPA_COMMIT();

    for (int kt = 0; kt < 32; kt++) {
        const int k0 = kt * 64;
        const int bf = kt & 1;
        // prefetch kt+1 into alternate buffer
        if (kt < 31) {
            const int k1 = k0 + 64;
            const int nbf = bf ^ 1;
            u32 kdst = sbase + SKB + nbf * SK_BYTES + krow * 272 + kchunk * 16;
            u32 vdst = sbase + SVB + nbf * SV_BYTES + vrow * 144 + vchunk * 16;
            #pragma unroll
            for (int it = 0; it < 4; it++)
                cpa16(kdst + it * 64, &Kg[(size_t)(k1 + krow) * HDIM + (kchunk + 4 * it) * 8]);
            #pragma unroll
            for (int it = 0; it < 4; it++)
                cpa16(vdst + it * 32, &Vg[(size_t)vrow * SS + k1 + (vchunk + 2 * it) * 8]);
        }
        CPA_COMMIT();
        CPA_WAIT1();
        __syncthreads();   // tile kt resident in buffer bf; prior PV reads of sP done

        const u32* sK = (const u32*)(smc + SKB + bf * SK_BYTES);
        const u32* sV = (const u32*)(smc + SVB + bf * SV_BYTES);

        // QK^T (A = registers, B = sK)
        float acc[2][4][4];
        #pragma unroll
        for (int mt = 0; mt < 2; mt++)
            #pragma unroll
            for (int nt = 0; nt < 4; nt++)
                #pragma unroll
                for (int c = 0; c < 4; c++) acc[mt][nt][c] = 0.0f;
        #pragma unroll
        for (int kk = 0; kk < 8; kk++) {
            #pragma unroll
            for (int nt = 0; nt < 4; nt++) {
                int key = 32 * cw + 8 * nt + g;
                u32 b0 = sK[key * 68 + 8 * kk + q4];
                u32 b1 = sK[key * 68 + 8 * kk + q4 + 4];
                mma_f16(acc[0][nt], qf[0][kk][0], qf[0][kk][1], qf[0][kk][2], qf[0][kk][3], b0, b1);
                mma_f16(acc[1][nt], qf[1][kk][0], qf[1][kk][1], qf[1][kk][2], qf[1][kk][3], b0, b1);
            }
        }

        // softmax epilogue (max-free, exp2 domain)
        #pragma unroll
        for (int mt = 0; mt < 2; mt++) {
            int row0 = 32 * rw + 16 * mt + g;
            #pragma unroll
            for (int nt = 0; nt < 4; nt++) {
                const float* mp = &mbase[(size_t)(q0 + row0) * SS + k0 + 32 * cw + 8 * nt + 2 * q4];
                float2 m0 = *(const float2*)mp;
                float2 m1 = *(const float2*)(mp + 8 * SS);
                float e0 = exp2f(acc[mt][nt][0] + m0.x * LOG2E - EOFF);
                float e1 = exp2f(acc[mt][nt][1] + m0.y * LOG2E - EOFF);
                float e2 = exp2f(acc[mt][nt][2] + m1.x * LOG2E - EOFF);
                float e3 = exp2f(acc[mt][nt][3] + m1.y * LOG2E - EOFF);
                rsum[mt][0] += e0 + e1;
                rsum[mt][1] += e2 + e3;
                sP[row0 * 36 + 16 * cw + 4 * nt + q4] = h2(e0, e1);
                sP[(row0 + 8) * 36 + 16 * cw + 4 * nt + q4] = h2(e2, e3);
            }
        }
        __syncthreads();   // P complete

        // PV (A = sP, B = sV)
        #pragma unroll
        for (int kk = 0; kk < 4; kk++) {
            u32 a[2][4];
            #pragma unroll
            for (int mt = 0; mt < 2; mt++) {
                int row0 = 32 * rw + 16 * mt + g;
                a[mt][0] = sP[row0 * 36 + q4 + 8 * kk];
                a[mt][1] = sP[(row0 + 8) * 36 + q4 + 8 * kk];
                a[mt][2] = sP[row0 * 36 + q4 + 4 + 8 * kk];
                a[mt][3] = sP[(row0 + 8) * 36 + q4 + 4 + 8 * kk];
            }
            #pragma unroll
            for (int nt = 0; nt < 8; nt++) {
                int d = 64 * cw + 8 * nt + g;
                u32 b0 = sV[d * 36 + q4 + 8 * kk];
                u32 b1 = sV[d * 36 + q4 + 4 + 8 * kk];
                mma_f16(o[0][nt], a[0][0], a[0][1], a[0][2], a[0][3], b0, b1);
                mma_f16(o[1][nt], a[1][0], a[1][1], a[1][2], a[1][3], b0, b1);
            }
        }
    }

    // finalize
    #pragma unroll
    for (int mt = 0; mt < 2; mt++)
        #pragma unroll
        for (int half = 0; half < 2; half++) {
            float s = rsum[mt][half];
            s += __shfl_xor_sync(0xffffffffu, s, 1);
            s += __shfl_xor_sync(0xffffffffu, s, 2);
            rsum[mt][half] = s;
        }
    if (q4 == 0) {
        #pragma unroll
        for (int mt = 0; mt < 2; mt++) {
            sL[cw * 128 + 32 * rw + 16 * mt + g] = rsum[mt][0];
            sL[cw * 128 + 32 * rw + 16 * mt + g + 8] = rsum[mt][1];
        }
    }
    __syncthreads();

    #pragma unroll
    for (int mt = 0; mt < 2; mt++) {
        int row0 = 32 * rw + 16 * mt + g;
        float inv0 = 1.0f / (sL[row0] + sL[128 + row0]);
        float inv1 = 1.0f / (sL[row0 + 8] + sL[128 + row0 + 8]);
        #pragma unroll
        for (int nt = 0; nt < 8; nt++) {
            int d = 64 * cw + 8 * nt + 2 * q4;
            size_t ob0 = (size_t)(b * SS + q0 + row0) * (HH * HDIM) + h * HDIM + d;
            size_t ob1 = (size_t)(b * SS + q0 + row0 + 8) * (HH * HDIM) + h * HDIM + d;
            *(float2*)&g_attn[ob0] = make_float2(o[mt][nt][0] * inv0, o[mt][nt][1] * inv0);
            *(float2*)&g_attn[ob1] = make_float2(o[mt][nt][2] * inv1, o[mt][nt][3] * inv1);
        }
    }
}

// ---------------------------------------------------------------------------
// Kernel 4a: output projection, fp16 mma, split-K=4. grid (32, 3, 4).
// ---------------------------------------------------------------------------
__global__ __launch_bounds__(256) void oproj_part_kernel(const float* __restrict__ wo)
{
    __shared__ u32 sA[128 * 36];
    __shared__ u32 sB[64 * 36];
    const int tid = threadIdx.x;
    const int wid = tid >> 5, lane = tid & 31;
    const int g = lane >> 2, q4 = lane & 3;
    const int rw = wid & 3, cw = wid >> 2;
    const int m0 = blockIdx.x * 128;
    const int n0 = blockIdx.y * 64;
    const int kt = blockIdx.z;

    float acc[2][4][4];
    #pragma unroll
    for (int mt = 0; mt < 2; mt++)
        #pragma unroll
        for (int nt = 0; nt < 4; nt++)
            #pragma unroll
            for (int c = 0; c < 4; c++) acc[mt][nt][c] = 0.0f;

    for (int kb = kt * 512; kb < kt * 512 + 512; kb += 64) {
        __syncthreads();
        #pragma unroll
        for (int it = 0; it < 8; it++) {
            int idx = tid + it * 256;
            int r = idx >> 4, l = idx & 15;
            float4 v = *(const float4*)&g_attn[(size_t)(m0 + r) * 2048 + kb + 4 * l];
            sA[r * 36 + 2 * l] = h2(v.x, v.y);
            sA[r * 36 + 2 * l + 1] = h2(v.z, v.w);
        }
        #pragma unroll
        for (int it = 0; it < 4; it++) {
            int idx = tid + it * 256;
            int r = idx >> 4, l = idx & 15;
            float4 v = *(const float4*)&wo[(size_t)(n0 + r) * 2048 + kb + 4 * l];
            sB[r * 36 + 2 * l] = h2(v.x, v.y);
            sB[r * 36 + 2 * l + 1] = h2(v.z, v.w);
        }
        __syncthreads();
        #pragma unroll
        for (int kk = 0; kk < 4; kk++) {
            u32 a[2][4];
            #pragma unroll
            for (int mt = 0; mt < 2; mt++) {
                int base = (32 * rw + 16 * mt + g) * 36 + 8 * kk + q4;
                a[mt][0] = sA[base];
                a[mt][1] = sA[base + 288];
                a[mt][2] = sA[base + 4];
                a[mt][3] = sA[base + 292];
            }
            #pragma unroll
            for (int nt = 0; nt < 4; nt++) {
                int nb = (32 * cw + 8 * nt + g) * 36 + 8 * kk + q4;
                u32 b0 = sB[nb], b1 = sB[nb + 4];
                mma_f16(acc[0][nt], a[0][0], a[0][1], a[0][2], a[0][3], b0, b1);
                mma_f16(acc[1][nt], a[1][0], a[1][1], a[1][2], a[1][3], b0, b1);
            }
        }
    }

    #pragma unroll
    for (int mt = 0; mt < 2; mt++) {
        int mrow = m0 + 32 * rw + 16 * mt + g;
        #pragma unroll
        for (int nt = 0; nt < 4; nt++) {
            int n = n0 + 32 * cw + 8 * nt + 2 * q4;
            float* pp = &g_part[kt][(size_t)mrow * DD + n];
            *(float2*)pp = make_float2(acc[mt][nt][0], acc[mt][nt][1]);
            *(float2*)(pp + 8 * DD) = make_float2(acc[mt][nt][2], acc[mt][nt][3]);
        }
    }
}

__global__ __launch_bounds__(256) void oproj_reduce_kernel(float* __restrict__ out)
{
    int idx = blockIdx.x * 256 + threadIdx.x;
    if (idx < (BB * SS * DD) / 4) {
        float4 a = *(const float4*)&g_part[0][idx * 4];
        float4 b = *(const float4*)&g_part[1][idx * 4];
        float4 c = *(const float4*)&g_part[2][idx * 4];
        float4 d = *(const float4*)&g_part[3][idx * 4];
        *(float4*)&out[idx * 4] = make_float4(a.x + b.x + c.x + d.x, a.y + b.y + c.y + d.y,
                                              a.z + b.z + c.z + d.z, a.w + b.w + c.w + d.w);
    }
}

// ---------------------------------------------------------------------------
// Inputs: x, mask0, wq, wk, wv, wo, q_norm_w, k_norm_w
// ---------------------------------------------------------------------------
extern "C" void kernel_launch(void* const* d_in, const int* in_sizes, int n_in,
                              void* d_out, int out_size)
{
    const float* x     = (const float*)d_in[0];
    const float* mask0 = (const float*)d_in[1];
    const float* wq    = (const float*)d_in[2];
    const float* wk    = (const float*)d_in[3];
    const float* wv    = (const float*)d_in[4];
    const float* wo    = (const float*)d_in[5];
    const float* qnw   = (const float*)d_in[6];
    const float* knw   = (const float*)d_in[7];
    float* out = (float*)d_out;

    cudaFuncSetAttribute(qkv_kernel, cudaFuncAttributeMaxDynamicSharedMemorySize, QKV_SMEM);
    cudaFuncSetAttribute(attn_kernel, cudaFuncAttributeMaxDynamicSharedMemorySize, AT_SMEM);

    rope_init_kernel<<<SS * 64 / 256, 256>>>();
    qkv_kernel<<<dim3(32, 32, 3), 256, QKV_SMEM>>>(x, wq, wk, wv);
    vtrans_kernel<<<dim3(SS / 64, HDIM / 64, BB * HH), 256>>>();
    normrope_kernel<<<BB * SS * HH, 128>>>(qnw, knw);
    attn_kernel<<<dim3(SS / 128, HH, BB), 256, AT_SMEM>>>(mask0);
    oproj_part_kernel<<<dim3(32, 3, 4), 256>>>(wo);
    oproj_reduce_kernel<<<768, 256>>>(out);
}